// round 2
// baseline (speedup 1.0000x reference)
#include <cuda_runtime.h>
#include <math.h>
#include <stdint.h>

// Problem constants (fixed by the dataset)
#define BB 128   // envs (n_seq)
#define TT 512   // timesteps
#define DD 512   // feature dim
#define HH 512   // lstm hidden
#define G4 2048  // 4*H gates
#define NR (BB*TT)   // 65536 rows
#define AA 32    // actions

// ---------------- scratch (device globals; no runtime allocation) ----------------
__device__ float g_Gpi[(size_t)NR * G4];   // 512 MB: x@Wih_pi.T + biases
__device__ float g_Gvf[(size_t)NR * G4];   // 512 MB
__device__ float g_Ypi[(size_t)NR * HH];   // lstm pi outputs over time
__device__ float g_Yvf[(size_t)NR * HH];
__device__ float g_Z1 [(size_t)NR * HH];   // shared hidden scratch (pi then vf)
__device__ float g_Z2pi[(size_t)NR * HH];
__device__ float g_Z2vf[(size_t)NR * HH];
__device__ float g_hbuf[2 * 2 * BB * HH];  // [lstm][pingpong][B*H]
__device__ unsigned g_bar_count;
__device__ unsigned g_bar_gen;

// ---------------- helpers ----------------
__device__ __forceinline__ float sigf(float x) { return 1.0f / (1.0f + __expf(-x)); }

// software grid barrier (persistent kernel, all CTAs co-resident)
__device__ __forceinline__ void grid_bar(int nct) {
    __syncthreads();
    if (threadIdx.x == 0) {
        __threadfence();
        volatile unsigned* vgen = &g_bar_gen;
        unsigned g = *vgen;
        unsigned a = atomicAdd(&g_bar_count, 1u);
        if (a == (unsigned)nct - 1u) {
            g_bar_count = 0u;
            __threadfence();
            atomicAdd(&g_bar_gen, 1u);
        } else {
            while (*vgen == g) { }
        }
        __threadfence();
    }
    __syncthreads();
}

// ---------------- generic fp32 GEMM:  C[M,N] = A[M,K] @ W[N,K]^T + b1 + b2 (opt relu) ----------------
// 128x128 block tile, BK=16, 256 threads, 8x8 per-thread microtile. All dims divide exactly.
__global__ __launch_bounds__(256) void sgemm_nt(
    const float* __restrict__ A, const float* __restrict__ W,
    const float* __restrict__ bias1, const float* __restrict__ bias2,
    float* __restrict__ C, int M, int N, int K, int relu)
{
    __shared__ float As[16][132];
    __shared__ float Bs[16][132];
    const int tx = threadIdx.x;
    const int tm = tx >> 4;   // 0..15
    const int tn = tx & 15;   // 0..15
    const size_t arow0 = (size_t)blockIdx.y * 128;
    const size_t brow0 = (size_t)blockIdx.x * 128;
    const float* Ab = A + arow0 * (size_t)K;
    const float* Wb = W + brow0 * (size_t)K;

    float acc[8][8];
#pragma unroll
    for (int i = 0; i < 8; i++)
#pragma unroll
        for (int j = 0; j < 8; j++) acc[i][j] = 0.0f;

    for (int k0 = 0; k0 < K; k0 += 16) {
#pragma unroll
        for (int r = 0; r < 2; r++) {
            int idx = tx + r * 256;       // 0..511
            int row = idx >> 2;           // 0..127
            int kq  = (idx & 3) << 2;     // 0,4,8,12
            float4 a4 = *(const float4*)(Ab + (size_t)row * K + k0 + kq);
            As[kq + 0][row] = a4.x; As[kq + 1][row] = a4.y;
            As[kq + 2][row] = a4.z; As[kq + 3][row] = a4.w;
            float4 b4 = *(const float4*)(Wb + (size_t)row * K + k0 + kq);
            Bs[kq + 0][row] = b4.x; Bs[kq + 1][row] = b4.y;
            Bs[kq + 2][row] = b4.z; Bs[kq + 3][row] = b4.w;
        }
        __syncthreads();
#pragma unroll
        for (int kk = 0; kk < 16; kk++) {
            float a[8], b[8];
            *(float4*)&a[0] = *(const float4*)&As[kk][tm * 8];
            *(float4*)&a[4] = *(const float4*)&As[kk][tm * 8 + 4];
            *(float4*)&b[0] = *(const float4*)&Bs[kk][tn * 8];
            *(float4*)&b[4] = *(const float4*)&Bs[kk][tn * 8 + 4];
#pragma unroll
            for (int i = 0; i < 8; i++)
#pragma unroll
                for (int j = 0; j < 8; j++)
                    acc[i][j] += a[i] * b[j];
        }
        __syncthreads();
    }

    float bb[8];
#pragma unroll
    for (int j = 0; j < 8; j++) {
        int col = (int)brow0 + tn * 8 + j;
        float v = bias1 ? bias1[col] : 0.0f;
        if (bias2) v += bias2[col];
        bb[j] = v;
    }
#pragma unroll
    for (int i = 0; i < 8; i++) {
        size_t row = arow0 + (size_t)(tm * 8 + i);
        float o[8];
#pragma unroll
        for (int j = 0; j < 8; j++) {
            float v = acc[i][j] + bb[j];
            o[j] = relu ? fmaxf(v, 0.0f) : v;
        }
        float* Cp = C + row * (size_t)N + brow0 + tn * 8;
        *(float4*)(Cp + 0) = make_float4(o[0], o[1], o[2], o[3]);
        *(float4*)(Cp + 4) = make_float4(o[4], o[5], o[6], o[7]);
    }
}

// ---------------- persistent recurrent kernel: both LSTMs, 512 steps ----------------
// 128 CTAs x 256 thr, 1 CTA/SM (smem-forced). CTA ct: lstm = ct/64, owns 8 h-cols
// (hc0 = (ct%64)*8) and their 4 gate rows each (32 gate-cols). c is CTA-local in smem.
// h ping-pongs through a global buffer with one grid barrier per step.
__global__ __launch_bounds__(256, 1) void lstm_recur(
    const float* __restrict__ Gpi, const float* __restrict__ Gvf,
    const float* __restrict__ starts,
    const float* __restrict__ h0pi, const float* __restrict__ c0pi,
    const float* __restrict__ h0vf, const float* __restrict__ c0vf,
    const float* __restrict__ Whhpi, const float* __restrict__ Whhvf,
    float* __restrict__ Ypi, float* __restrict__ Yvf,
    float* __restrict__ hbuf, float* __restrict__ out)
{
    extern __shared__ float smem[];
    float* sW = smem;                 // [512][32]  sW[k*32+j] = Whh[gcol(j)][k]
    float* sh = sW + 512 * 32;        // [32][129]  h chunk, transposed, masked
    float* sg = sh + 32 * 129;        // [128][33]  gate preactivations
    float* sc = sg + 128 * 33;        // [128][8]   cell state (persistent)
    float* sm = sc + 128 * 8;         // [128]      1 - episode_start

    const int ct   = blockIdx.x;
    const int lstm = ct >> 6;
    const int cid  = ct & 63;
    const int hc0  = cid * 8;
    const int tx   = threadIdx.x;
    const int trow = tx >> 3;         // 0..31
    const int tcol = tx & 7;          // 0..7

    const float* Gx  = lstm ? Gvf   : Gpi;
    const float* Whh = lstm ? Whhvf : Whhpi;
    const float* h0  = lstm ? h0vf  : h0pi;
    const float* c0  = lstm ? c0vf  : c0pi;
    float* Y  = lstm ? Yvf : Ypi;
    float* hb = hbuf + lstm * 2 * BB * HH;

    // load this CTA's 32 Whh rows (transposed into sW)
    for (int idx = tx; idx < 32 * 512; idx += 256) {
        int j = idx >> 9;             // local gate col 0..31
        int k = idx & 511;
        int gc = ((j >> 3) << 9) + hc0 + (j & 7);   // global gate row
        sW[k * 32 + j] = Whh[(size_t)gc * HH + k];
    }
    // init h (global ping buffer 0) and c (smem)
    for (int idx = tx; idx < BB * 8; idx += 256) {
        int b = idx >> 3, q = idx & 7;
        hb[b * HH + hc0 + q] = h0[b * HH + hc0 + q];
        sc[b * 8 + q]        = c0[b * HH + hc0 + q];
    }
    __threadfence();
    grid_bar(gridDim.x);

    for (int t = 0; t < TT; t++) {
        const int cur = t & 1, nxt = cur ^ 1;
        if (tx < BB) sm[tx] = 1.0f - starts[tx * TT + t];
        __syncthreads();

        float acc[4][4];
#pragma unroll
        for (int i = 0; i < 4; i++)
#pragma unroll
            for (int j = 0; j < 4; j++) acc[i][j] = 0.0f;

        const float* hc = hb + cur * BB * HH;
        for (int k0 = 0; k0 < HH; k0 += 32) {
            // stage masked h chunk transposed: sh[k][b] = h[b][k0+k] * m[b]
#pragma unroll
            for (int r = 0; r < 4; r++) {
                int f4 = tx + r * 256;        // 0..1023
                int b  = f4 >> 3;
                int kq = (f4 & 7) << 2;
                float4 v = *(const float4*)(hc + b * HH + k0 + kq);
                float m = sm[b];
                sh[(kq + 0) * 129 + b] = v.x * m;
                sh[(kq + 1) * 129 + b] = v.y * m;
                sh[(kq + 2) * 129 + b] = v.z * m;
                sh[(kq + 3) * 129 + b] = v.w * m;
            }
            __syncthreads();
#pragma unroll
            for (int kk = 0; kk < 32; kk++) {
                float4 w4 = *(const float4*)&sW[(k0 + kk) * 32 + tcol * 4];
                float h0v = sh[kk * 129 + trow * 4 + 0];
                float h1v = sh[kk * 129 + trow * 4 + 1];
                float h2v = sh[kk * 129 + trow * 4 + 2];
                float h3v = sh[kk * 129 + trow * 4 + 3];
                acc[0][0] += h0v * w4.x; acc[0][1] += h0v * w4.y; acc[0][2] += h0v * w4.z; acc[0][3] += h0v * w4.w;
                acc[1][0] += h1v * w4.x; acc[1][1] += h1v * w4.y; acc[1][2] += h1v * w4.z; acc[1][3] += h1v * w4.w;
                acc[2][0] += h2v * w4.x; acc[2][1] += h2v * w4.y; acc[2][2] += h2v * w4.z; acc[2][3] += h2v * w4.w;
                acc[3][0] += h3v * w4.x; acc[3][1] += h3v * w4.y; acc[3][2] += h3v * w4.z; acc[3][3] += h3v * w4.w;
            }
            __syncthreads();
        }

        // add precomputed x-part and publish gate preactivations to smem
        {
            int gcb = ((tcol >> 1) << 9) + hc0 + ((tcol & 1) << 2);
#pragma unroll
            for (int i = 0; i < 4; i++) {
                int b = trow * 4 + i;
                float4 gx = *(const float4*)(Gx + (size_t)(b * TT + t) * G4 + gcb);
                sg[b * 33 + tcol * 4 + 0] = acc[i][0] + gx.x;
                sg[b * 33 + tcol * 4 + 1] = acc[i][1] + gx.y;
                sg[b * 33 + tcol * 4 + 2] = acc[i][2] + gx.z;
                sg[b * 33 + tcol * 4 + 3] = acc[i][3] + gx.w;
            }
        }
        __syncthreads();

        // elementwise LSTM update (gate order i,f,g,o)
        {
            int b  = tx >> 1;
            int kb = (tx & 1) << 2;
            float m = sm[b];
            float hout[4];
#pragma unroll
            for (int i = 0; i < 4; i++) {
                int kk = kb + i;
                float gi = sg[b * 33 + kk];
                float gf = sg[b * 33 + 8 + kk];
                float gz = sg[b * 33 + 16 + kk];
                float go = sg[b * 33 + 24 + kk];
                float c  = sc[b * 8 + kk] * m;
                float cn = sigf(gf) * c + sigf(gi) * tanhf(gz);
                float hn = sigf(go) * tanhf(cn);
                sc[b * 8 + kk] = cn;
                hout[i] = hn;
            }
            float4 hv = make_float4(hout[0], hout[1], hout[2], hout[3]);
            *(float4*)(hb + nxt * BB * HH + b * HH + hc0 + kb) = hv;
            *(float4*)(Y + (size_t)(b * TT + t) * HH + hc0 + kb) = hv;
        }
        __threadfence();
        grid_bar(gridDim.x);
    }

    // final h (in ping buffer 0 after 512 steps) and c -> d_out
    float* oh = out + (size_t)3 * NR + (size_t)lstm * 2 * NR;
    float* oc = oh + NR;
    for (int idx = tx; idx < BB * 8; idx += 256) {
        int b = idx >> 3, q = idx & 7;
        oh[b * HH + hc0 + q] = hb[0 * BB * HH + b * HH + hc0 + q];
        oc[b * HH + hc0 + q] = sc[b * 8 + q];
    }
}

// ---------------- heads: logits/argmax/log_prob + value, one block per row ----------------
__global__ __launch_bounds__(128) void head_kernel(
    const float* __restrict__ Zpi, const float* __restrict__ Zvf,
    const float* __restrict__ aw, const float* __restrict__ ab,
    const float* __restrict__ cw, const float* __restrict__ cb,
    float* __restrict__ out)
{
    __shared__ float sx[512];
    __shared__ float slog[32];
    __shared__ float sval[4];
    const int n  = blockIdx.x;
    const int tx = threadIdx.x;

    ((float4*)sx)[tx] = ((const float4*)(Zpi + (size_t)n * 512))[tx];

    // critic dot (from Zvf row, direct)
    float4 xv = ((const float4*)(Zvf + (size_t)n * 512))[tx];
    float4 wv = ((const float4*)cw)[tx];
    float v = xv.x * wv.x + xv.y * wv.y + xv.z * wv.z + xv.w * wv.w;
#pragma unroll
    for (int off = 16; off; off >>= 1) v += __shfl_xor_sync(0xffffffffu, v, off);
    if ((tx & 31) == 0) sval[tx >> 5] = v;
    __syncthreads();

    // 32 logits, 4 threads per logit
    const int l = tx >> 2;
    const int part = tx & 3;
    const float* wl = aw + l * 512 + part * 128;
    const float* xl = sx + part * 128;
    float s = 0.0f;
#pragma unroll 8
    for (int k4 = 0; k4 < 32; k4++) {
        float4 a = ((const float4*)xl)[k4];
        float4 w = ((const float4*)wl)[k4];
        s += a.x * w.x + a.y * w.y + a.z * w.z + a.w * w.w;
    }
    s += __shfl_xor_sync(0xffffffffu, s, 1);
    s += __shfl_xor_sync(0xffffffffu, s, 2);
    if (part == 0) slog[l] = s + ab[l];
    __syncthreads();

    if (tx < 32) {
        float lv = slog[tx];
        float m = lv; int mi = tx;
#pragma unroll
        for (int off = 16; off; off >>= 1) {
            float om = __shfl_xor_sync(0xffffffffu, m, off);
            int   oi = __shfl_xor_sync(0xffffffffu, mi, off);
            if (om > m || (om == m && oi < mi)) { m = om; mi = oi; }
        }
        float e = __expf(lv - m);
#pragma unroll
        for (int off = 16; off; off >>= 1) e += __shfl_xor_sync(0xffffffffu, e, off);
        if (tx == 0) {
            out[n] = (float)mi;                                          // actions
            out[(size_t)NR + n] = sval[0] + sval[1] + sval[2] + sval[3] + cb[0];  // values
            out[(size_t)2 * NR + n] = -__logf(e);                        // log_prob
        }
    }
}

// ---------------- launch ----------------
extern "C" void kernel_launch(void* const* d_in, const int* in_sizes, int n_in,
                              void* d_out, int out_size)
{
    const float* features = (const float*)d_in[0];
    const float* starts   = (const float*)d_in[1];
    const float* h0pi = (const float*)d_in[2];
    const float* c0pi = (const float*)d_in[3];
    const float* h0vf = (const float*)d_in[4];
    const float* c0vf = (const float*)d_in[5];
    const float* Wihpi = (const float*)d_in[6];
    const float* Whhpi = (const float*)d_in[7];
    const float* bihpi = (const float*)d_in[8];
    const float* bhhpi = (const float*)d_in[9];
    const float* Wihvf = (const float*)d_in[10];
    const float* Whhvf = (const float*)d_in[11];
    const float* bihvf = (const float*)d_in[12];
    const float* bhhvf = (const float*)d_in[13];
    const float* polw1 = (const float*)d_in[14];
    const float* polb1 = (const float*)d_in[15];
    const float* polw2 = (const float*)d_in[16];
    const float* polb2 = (const float*)d_in[17];
    const float* valw1 = (const float*)d_in[18];
    const float* valb1 = (const float*)d_in[19];
    const float* valw2 = (const float*)d_in[20];
    const float* valb2 = (const float*)d_in[21];
    const float* aw = (const float*)d_in[22];
    const float* ab = (const float*)d_in[23];
    const float* cw = (const float*)d_in[24];
    const float* cb = (const float*)d_in[25];

    float *Gpi, *Gvf, *Ypi, *Yvf, *Z1, *Z2pi, *Z2vf, *hbuf;
    cudaGetSymbolAddress((void**)&Gpi,  g_Gpi);
    cudaGetSymbolAddress((void**)&Gvf,  g_Gvf);
    cudaGetSymbolAddress((void**)&Ypi,  g_Ypi);
    cudaGetSymbolAddress((void**)&Yvf,  g_Yvf);
    cudaGetSymbolAddress((void**)&Z1,   g_Z1);
    cudaGetSymbolAddress((void**)&Z2pi, g_Z2pi);
    cudaGetSymbolAddress((void**)&Z2vf, g_Z2vf);
    cudaGetSymbolAddress((void**)&hbuf, g_hbuf);
    float* out = (float*)d_out;

    dim3 thr(256);
    // phase 1: hoisted input GEMMs  G = X @ Wih^T + bih + bhh
    sgemm_nt<<<dim3(G4 / 128, NR / 128), thr>>>(features, Wihpi, bihpi, bhhpi, Gpi, NR, G4, DD, 0);
    sgemm_nt<<<dim3(G4 / 128, NR / 128), thr>>>(features, Wihvf, bihvf, bhhvf, Gvf, NR, G4, DD, 0);

    // phase 2: persistent recurrence (both LSTMs in one grid)
    size_t shm = (size_t)(512 * 32 + 32 * 129 + 128 * 33 + 128 * 8 + 128) * sizeof(float);
    cudaFuncSetAttribute((const void*)lstm_recur,
                         cudaFuncAttributeMaxDynamicSharedMemorySize, (int)shm);
    lstm_recur<<<128, 256, shm>>>(Gpi, Gvf, starts, h0pi, c0pi, h0vf, c0vf,
                                  Whhpi, Whhvf, Ypi, Yvf, hbuf, out);

    // phase 3: MLPs
    sgemm_nt<<<dim3(HH / 128, NR / 128), thr>>>(Ypi, polw1, polb1, nullptr, Z1,   NR, HH, HH, 1);
    sgemm_nt<<<dim3(HH / 128, NR / 128), thr>>>(Z1,  polw2, polb2, nullptr, Z2pi, NR, HH, HH, 0);
    sgemm_nt<<<dim3(HH / 128, NR / 128), thr>>>(Yvf, valw1, valb1, nullptr, Z1,   NR, HH, HH, 1);
    sgemm_nt<<<dim3(HH / 128, NR / 128), thr>>>(Z1,  valw2, valb2, nullptr, Z2vf, NR, HH, HH, 0);

    // phase 4: heads
    head_kernel<<<NR, 128>>>(Z2pi, Z2vf, aw, ab, cw, cb, out);
}

// round 3
// speedup vs baseline: 1.0458x; 1.0458x over previous
#include <cuda_runtime.h>
#include <math.h>
#include <stdint.h>

// Problem constants (fixed by the dataset)
#define BB 128   // envs (n_seq)
#define TT 512   // timesteps
#define DD 512   // feature dim
#define HH 512   // lstm hidden
#define G4 2048  // 4*H gates
#define NR (BB*TT)   // 65536 rows
#define AA 32    // actions

typedef unsigned long long ull;

// packed fp32x2 helpers (sm_100+ PTX)
#define FMA2(c,a,b)   asm("fma.rn.f32x2 %0, %1, %2, %0;" : "+l"(c) : "l"(a), "l"(b))
#define PACK2(d,x)    asm("mov.b64 %0, {%1, %1};" : "=l"(d) : "f"(x))
#define UNPK2(lo,hi,p) asm("mov.b64 {%0, %1}, %2;" : "=f"(lo), "=f"(hi) : "l"(p))

// ---------------- scratch (device globals; no runtime allocation) ----------------
__device__ float g_Gpi[(size_t)NR * G4];
__device__ float g_Gvf[(size_t)NR * G4];
__device__ float g_Ypi[(size_t)NR * HH];
__device__ float g_Yvf[(size_t)NR * HH];
__device__ float g_Z1 [(size_t)NR * HH];
__device__ float g_Z1b[(size_t)NR * HH];
__device__ float g_Z2pi[(size_t)NR * HH];
__device__ float g_Z2vf[(size_t)NR * HH];
__device__ float g_hbuf[2 * 2 * BB * HH];
__device__ unsigned g_bar_count;
__device__ unsigned g_bar_gen;

__device__ __forceinline__ float sigf(float x) { return 1.0f / (1.0f + __expf(-x)); }

// software grid barrier (persistent kernel, all CTAs co-resident)
__device__ __forceinline__ void grid_bar(int nct) {
    __syncthreads();
    if (threadIdx.x == 0) {
        __threadfence();
        volatile unsigned* vgen = &g_bar_gen;
        unsigned g = *vgen;
        unsigned a = atomicAdd(&g_bar_count, 1u);
        if (a == (unsigned)nct - 1u) {
            g_bar_count = 0u;
            __threadfence();
            atomicAdd(&g_bar_gen, 1u);
        } else {
            while (*vgen == g) { }
        }
        __threadfence();
    }
    __syncthreads();
}

// ---------------- fp32 GEMM with f32x2 + double buffering ----------------
// C[M,N] = A[M,K] @ W[N,K]^T + b1 + b2 (opt relu). 128x128x16 tile, 256 thr, 8x8/thread.
__global__ __launch_bounds__(256) void sgemm_nt(
    const float* __restrict__ A, const float* __restrict__ W,
    const float* __restrict__ bias1, const float* __restrict__ bias2,
    float* __restrict__ C, int M, int N, int K, int relu)
{
    __shared__ float As[2][16][132];
    __shared__ float Bs[2][16][132];
    const int tx = threadIdx.x;
    const int tm = tx >> 4;   // 0..15
    const int tn = tx & 15;   // 0..15
    const size_t arow0 = (size_t)blockIdx.y * 128;
    const size_t brow0 = (size_t)blockIdx.x * 128;
    const float* Ab = A + arow0 * (size_t)K;
    const float* Wb = W + brow0 * (size_t)K;
    const int lrow0 = tx >> 2;            // 0..63
    const int lkq   = (tx & 3) << 2;      // 0,4,8,12
    const int lrow1 = lrow0 + 64;

    ull acc2[8][4];
#pragma unroll
    for (int i = 0; i < 8; i++)
#pragma unroll
        for (int j = 0; j < 4; j++) acc2[i][j] = 0ull;

    float4 pa0, pa1, pb0, pb1;
    // prefetch k-chunk 0
    pa0 = *(const float4*)(Ab + (size_t)lrow0 * K + lkq);
    pb0 = *(const float4*)(Wb + (size_t)lrow0 * K + lkq);
    pa1 = *(const float4*)(Ab + (size_t)lrow1 * K + lkq);
    pb1 = *(const float4*)(Wb + (size_t)lrow1 * K + lkq);
    As[0][lkq+0][lrow0]=pa0.x; As[0][lkq+1][lrow0]=pa0.y; As[0][lkq+2][lrow0]=pa0.z; As[0][lkq+3][lrow0]=pa0.w;
    Bs[0][lkq+0][lrow0]=pb0.x; Bs[0][lkq+1][lrow0]=pb0.y; Bs[0][lkq+2][lrow0]=pb0.z; Bs[0][lkq+3][lrow0]=pb0.w;
    As[0][lkq+0][lrow1]=pa1.x; As[0][lkq+1][lrow1]=pa1.y; As[0][lkq+2][lrow1]=pa1.z; As[0][lkq+3][lrow1]=pa1.w;
    Bs[0][lkq+0][lrow1]=pb1.x; Bs[0][lkq+1][lrow1]=pb1.y; Bs[0][lkq+2][lrow1]=pb1.z; Bs[0][lkq+3][lrow1]=pb1.w;
    __syncthreads();

    const int nk = K >> 4;
    for (int c = 0; c < nk; c++) {
        const int buf = c & 1;
        if (c + 1 < nk) {
            const int k0 = (c + 1) << 4;
            pa0 = *(const float4*)(Ab + (size_t)lrow0 * K + k0 + lkq);
            pb0 = *(const float4*)(Wb + (size_t)lrow0 * K + k0 + lkq);
            pa1 = *(const float4*)(Ab + (size_t)lrow1 * K + k0 + lkq);
            pb1 = *(const float4*)(Wb + (size_t)lrow1 * K + k0 + lkq);
        }
#pragma unroll
        for (int kk = 0; kk < 16; kk++) {
            float4 a0 = *(const float4*)&As[buf][kk][tm * 8];
            float4 a1 = *(const float4*)&As[buf][kk][tm * 8 + 4];
            const float* bp = &Bs[buf][kk][tn * 8];
            ull b0 = *(const ull*)(bp + 0);
            ull b1 = *(const ull*)(bp + 2);
            ull b2 = *(const ull*)(bp + 4);
            ull b3 = *(const ull*)(bp + 6);
            ull ap;
            PACK2(ap, a0.x); FMA2(acc2[0][0],ap,b0); FMA2(acc2[0][1],ap,b1); FMA2(acc2[0][2],ap,b2); FMA2(acc2[0][3],ap,b3);
            PACK2(ap, a0.y); FMA2(acc2[1][0],ap,b0); FMA2(acc2[1][1],ap,b1); FMA2(acc2[1][2],ap,b2); FMA2(acc2[1][3],ap,b3);
            PACK2(ap, a0.z); FMA2(acc2[2][0],ap,b0); FMA2(acc2[2][1],ap,b1); FMA2(acc2[2][2],ap,b2); FMA2(acc2[2][3],ap,b3);
            PACK2(ap, a0.w); FMA2(acc2[3][0],ap,b0); FMA2(acc2[3][1],ap,b1); FMA2(acc2[3][2],ap,b2); FMA2(acc2[3][3],ap,b3);
            PACK2(ap, a1.x); FMA2(acc2[4][0],ap,b0); FMA2(acc2[4][1],ap,b1); FMA2(acc2[4][2],ap,b2); FMA2(acc2[4][3],ap,b3);
            PACK2(ap, a1.y); FMA2(acc2[5][0],ap,b0); FMA2(acc2[5][1],ap,b1); FMA2(acc2[5][2],ap,b2); FMA2(acc2[5][3],ap,b3);
            PACK2(ap, a1.z); FMA2(acc2[6][0],ap,b0); FMA2(acc2[6][1],ap,b1); FMA2(acc2[6][2],ap,b2); FMA2(acc2[6][3],ap,b3);
            PACK2(ap, a1.w); FMA2(acc2[7][0],ap,b0); FMA2(acc2[7][1],ap,b1); FMA2(acc2[7][2],ap,b2); FMA2(acc2[7][3],ap,b3);
        }
        if (c + 1 < nk) {
            const int nb = buf ^ 1;
            As[nb][lkq+0][lrow0]=pa0.x; As[nb][lkq+1][lrow0]=pa0.y; As[nb][lkq+2][lrow0]=pa0.z; As[nb][lkq+3][lrow0]=pa0.w;
            Bs[nb][lkq+0][lrow0]=pb0.x; Bs[nb][lkq+1][lrow0]=pb0.y; Bs[nb][lkq+2][lrow0]=pb0.z; Bs[nb][lkq+3][lrow0]=pb0.w;
            As[nb][lkq+0][lrow1]=pa1.x; As[nb][lkq+1][lrow1]=pa1.y; As[nb][lkq+2][lrow1]=pa1.z; As[nb][lkq+3][lrow1]=pa1.w;
            Bs[nb][lkq+0][lrow1]=pb1.x; Bs[nb][lkq+1][lrow1]=pb1.y; Bs[nb][lkq+2][lrow1]=pb1.z; Bs[nb][lkq+3][lrow1]=pb1.w;
        }
        __syncthreads();
    }

    float bb[8];
#pragma unroll
    for (int j = 0; j < 8; j++) {
        int col = (int)brow0 + tn * 8 + j;
        float v = bias1 ? bias1[col] : 0.0f;
        if (bias2) v += bias2[col];
        bb[j] = v;
    }
#pragma unroll
    for (int i = 0; i < 8; i++) {
        size_t row = arow0 + (size_t)(tm * 8 + i);
        float o[8];
        UNPK2(o[0], o[1], acc2[i][0]);
        UNPK2(o[2], o[3], acc2[i][1]);
        UNPK2(o[4], o[5], acc2[i][2]);
        UNPK2(o[6], o[7], acc2[i][3]);
#pragma unroll
        for (int j = 0; j < 8; j++) {
            float v = o[j] + bb[j];
            o[j] = relu ? fmaxf(v, 0.0f) : v;
        }
        float* Cp = C + row * (size_t)N + brow0 + tn * 8;
        *(float4*)(Cp + 0) = make_float4(o[0], o[1], o[2], o[3]);
        *(float4*)(Cp + 4) = make_float4(o[4], o[5], o[6], o[7]);
    }
}

// ---------------- persistent recurrent kernel: both LSTMs, 512 steps ----------------
// 128 CTAs x 256 thr, 1 CTA/SM. CTA ct: lstm = ct/64, owns 8 h-cols (32 gate-cols).
// c stays CTA-local in smem; h ping-pongs through global with 1 grid barrier/step.
// f32x2 inner product + double-buffered h staging.
__global__ __launch_bounds__(256, 1) void lstm_recur(
    const float* __restrict__ Gpi, const float* __restrict__ Gvf,
    const float* __restrict__ starts,
    const float* __restrict__ h0pi, const float* __restrict__ c0pi,
    const float* __restrict__ h0vf, const float* __restrict__ c0vf,
    const float* __restrict__ Whhpi, const float* __restrict__ Whhvf,
    float* __restrict__ Ypi, float* __restrict__ Yvf,
    float* __restrict__ hbuf, float* __restrict__ out)
{
    extern __shared__ float smem[];
    float* sW  = smem;                    // [512][32]
    float* sh0 = sW + 512 * 32;           // [32][129] buffer 0
    float* sh1 = sh0 + 32 * 129;          // [32][129] buffer 1
    float* sg  = sh1 + 32 * 129;          // [128][33]
    float* sc  = sg + 128 * 33;           // [128][8]
    float* sm  = sc + 128 * 8;            // [128]

    const int ct   = blockIdx.x;
    const int lstm = ct >> 6;
    const int cid  = ct & 63;
    const int hc0  = cid * 8;
    const int tx   = threadIdx.x;
    const int trow = tx >> 3;             // 0..31 (batch group)
    const int tcol = tx & 7;              // 0..7  (local gate col group)

    const float* Gx  = lstm ? Gvf   : Gpi;
    const float* Whh = lstm ? Whhvf : Whhpi;
    const float* h0  = lstm ? h0vf  : h0pi;
    const float* c0  = lstm ? c0vf  : c0pi;
    float* Y  = lstm ? Yvf : Ypi;
    float* hb = hbuf + lstm * 2 * BB * HH;

    // staging indices (fixed per thread): 4 (b,kq) pairs
    int stb[4], stk[4];
#pragma unroll
    for (int r = 0; r < 4; r++) {
        int f4 = tx + r * 256;
        stb[r] = f4 >> 3;
        stk[r] = (f4 & 7) << 2;
    }

    // load this CTA's 32 Whh rows (transposed into sW)
    for (int idx = tx; idx < 32 * 512; idx += 256) {
        int j = idx >> 9;
        int k = idx & 511;
        int gc = ((j >> 3) << 9) + hc0 + (j & 7);
        sW[k * 32 + j] = Whh[(size_t)gc * HH + k];
    }
    for (int idx = tx; idx < BB * 8; idx += 256) {
        int b = idx >> 3, q = idx & 7;
        hb[b * HH + hc0 + q] = h0[b * HH + hc0 + q];
        sc[b * 8 + q]        = c0[b * HH + hc0 + q];
    }
    __threadfence();
    grid_bar(gridDim.x);

    for (int t = 0; t < TT; t++) {
        const int cur = t & 1, nxt = cur ^ 1;
        const float* hc = hb + cur * BB * HH;

        float4 pre[4];
        // prefetch chunk 0 (no mask yet)
#pragma unroll
        for (int r = 0; r < 4; r++)
            pre[r] = *(const float4*)(hc + stb[r] * HH + stk[r]);
        if (tx < BB) sm[tx] = 1.0f - starts[tx * TT + t];
        __syncthreads();
        // stage chunk 0 with mask
#pragma unroll
        for (int r = 0; r < 4; r++) {
            float m = sm[stb[r]];
            sh0[(stk[r] + 0) * 129 + stb[r]] = pre[r].x * m;
            sh0[(stk[r] + 1) * 129 + stb[r]] = pre[r].y * m;
            sh0[(stk[r] + 2) * 129 + stb[r]] = pre[r].z * m;
            sh0[(stk[r] + 3) * 129 + stb[r]] = pre[r].w * m;
        }
        __syncthreads();

        ull acc2[4][2];
#pragma unroll
        for (int i = 0; i < 4; i++) { acc2[i][0] = 0ull; acc2[i][1] = 0ull; }

#pragma unroll 1
        for (int c = 0; c < 16; c++) {
            const int k0 = c << 5;
            if (c < 15) {
#pragma unroll
                for (int r = 0; r < 4; r++)
                    pre[r] = *(const float4*)(hc + stb[r] * HH + k0 + 32 + stk[r]);
            }
            const float* shc = (c & 1) ? sh1 : sh0;
#pragma unroll
            for (int kk = 0; kk < 32; kk++) {
                const float* swp = &sW[(k0 + kk) * 32 + tcol * 4];
                ull w01 = *(const ull*)(swp + 0);
                ull w23 = *(const ull*)(swp + 2);
                const float* hv = &shc[kk * 129 + trow * 4];
                ull hp;
                PACK2(hp, hv[0]); FMA2(acc2[0][0], hp, w01); FMA2(acc2[0][1], hp, w23);
                PACK2(hp, hv[1]); FMA2(acc2[1][0], hp, w01); FMA2(acc2[1][1], hp, w23);
                PACK2(hp, hv[2]); FMA2(acc2[2][0], hp, w01); FMA2(acc2[2][1], hp, w23);
                PACK2(hp, hv[3]); FMA2(acc2[3][0], hp, w01); FMA2(acc2[3][1], hp, w23);
            }
            if (c < 15) {
                float* shn = (c & 1) ? sh0 : sh1;
#pragma unroll
                for (int r = 0; r < 4; r++) {
                    float m = sm[stb[r]];
                    shn[(stk[r] + 0) * 129 + stb[r]] = pre[r].x * m;
                    shn[(stk[r] + 1) * 129 + stb[r]] = pre[r].y * m;
                    shn[(stk[r] + 2) * 129 + stb[r]] = pre[r].z * m;
                    shn[(stk[r] + 3) * 129 + stb[r]] = pre[r].w * m;
                }
            }
            __syncthreads();
        }

        // add precomputed x-part; publish gate preactivations
        {
            int gcb = ((tcol >> 1) << 9) + hc0 + ((tcol & 1) << 2);
#pragma unroll
            for (int i = 0; i < 4; i++) {
                int b = trow * 4 + i;
                float4 gx = *(const float4*)(Gx + (size_t)(b * TT + t) * G4 + gcb);
                float a0, a1, a2, a3;
                UNPK2(a0, a1, acc2[i][0]);
                UNPK2(a2, a3, acc2[i][1]);
                sg[b * 33 + tcol * 4 + 0] = a0 + gx.x;
                sg[b * 33 + tcol * 4 + 1] = a1 + gx.y;
                sg[b * 33 + tcol * 4 + 2] = a2 + gx.z;
                sg[b * 33 + tcol * 4 + 3] = a3 + gx.w;
            }
        }
        __syncthreads();

        // elementwise LSTM update (gate order i,f,g,o)
        {
            int b  = tx >> 1;
            int kb = (tx & 1) << 2;
            float m = sm[b];
            float hout[4];
#pragma unroll
            for (int i = 0; i < 4; i++) {
                int kk = kb + i;
                float gi = sg[b * 33 + kk];
                float gf = sg[b * 33 + 8 + kk];
                float gz = sg[b * 33 + 16 + kk];
                float go = sg[b * 33 + 24 + kk];
                float cc = sc[b * 8 + kk] * m;
                float cn = sigf(gf) * cc + sigf(gi) * tanhf(gz);
                float hn = sigf(go) * tanhf(cn);
                sc[b * 8 + kk] = cn;
                hout[i] = hn;
            }
            float4 hv = make_float4(hout[0], hout[1], hout[2], hout[3]);
            *(float4*)(hb + nxt * BB * HH + b * HH + hc0 + kb) = hv;
            *(float4*)(Y + (size_t)(b * TT + t) * HH + hc0 + kb) = hv;
        }
        __threadfence();
        grid_bar(gridDim.x);
    }

    // final h (ping buffer 0 after 512 steps) and c -> d_out
    float* oh = out + (size_t)3 * NR + (size_t)lstm * 2 * NR;
    float* oc = oh + NR;
    for (int idx = tx; idx < BB * 8; idx += 256) {
        int b = idx >> 3, q = idx & 7;
        oh[b * HH + hc0 + q] = hb[0 * BB * HH + b * HH + hc0 + q];
        oc[b * HH + hc0 + q] = sc[b * 8 + q];
    }
}

// ---------------- heads ----------------
__global__ __launch_bounds__(128) void head_kernel(
    const float* __restrict__ Zpi, const float* __restrict__ Zvf,
    const float* __restrict__ aw, const float* __restrict__ ab,
    const float* __restrict__ cw, const float* __restrict__ cb,
    float* __restrict__ out)
{
    __shared__ float sx[512];
    __shared__ float slog[32];
    __shared__ float sval[4];
    const int n  = blockIdx.x;
    const int tx = threadIdx.x;

    ((float4*)sx)[tx] = ((const float4*)(Zpi + (size_t)n * 512))[tx];

    float4 xv = ((const float4*)(Zvf + (size_t)n * 512))[tx];
    float4 wv = ((const float4*)cw)[tx];
    float v = xv.x * wv.x + xv.y * wv.y + xv.z * wv.z + xv.w * wv.w;
#pragma unroll
    for (int off = 16; off; off >>= 1) v += __shfl_xor_sync(0xffffffffu, v, off);
    if ((tx & 31) == 0) sval[tx >> 5] = v;
    __syncthreads();

    const int l = tx >> 2;
    const int part = tx & 3;
    const float* wl = aw + l * 512 + part * 128;
    const float* xl = sx + part * 128;
    float s = 0.0f;
#pragma unroll 8
    for (int k4 = 0; k4 < 32; k4++) {
        float4 a = ((const float4*)xl)[k4];
        float4 w = ((const float4*)wl)[k4];
        s += a.x * w.x + a.y * w.y + a.z * w.z + a.w * w.w;
    }
    s += __shfl_xor_sync(0xffffffffu, s, 1);
    s += __shfl_xor_sync(0xffffffffu, s, 2);
    if (part == 0) slog[l] = s + ab[l];
    __syncthreads();

    if (tx < 32) {
        float lv = slog[tx];
        float m = lv; int mi = tx;
#pragma unroll
        for (int off = 16; off; off >>= 1) {
            float om = __shfl_xor_sync(0xffffffffu, m, off);
            int   oi = __shfl_xor_sync(0xffffffffu, mi, off);
            if (om > m || (om == m && oi < mi)) { m = om; mi = oi; }
        }
        float e = __expf(lv - m);
#pragma unroll
        for (int off = 16; off; off >>= 1) e += __shfl_xor_sync(0xffffffffu, e, off);
        if (tx == 0) {
            out[n] = (float)mi;
            out[(size_t)NR + n] = sval[0] + sval[1] + sval[2] + sval[3] + cb[0];
            out[(size_t)2 * NR + n] = -__logf(e);
        }
    }
}

// ---------------- launch ----------------
extern "C" void kernel_launch(void* const* d_in, const int* in_sizes, int n_in,
                              void* d_out, int out_size)
{
    const float* features = (const float*)d_in[0];
    const float* starts   = (const float*)d_in[1];
    const float* h0pi = (const float*)d_in[2];
    const float* c0pi = (const float*)d_in[3];
    const float* h0vf = (const float*)d_in[4];
    const float* c0vf = (const float*)d_in[5];
    const float* Wihpi = (const float*)d_in[6];
    const float* Whhpi = (const float*)d_in[7];
    const float* bihpi = (const float*)d_in[8];
    const float* bhhpi = (const float*)d_in[9];
    const float* Wihvf = (const float*)d_in[10];
    const float* Whhvf = (const float*)d_in[11];
    const float* bihvf = (const float*)d_in[12];
    const float* bhhvf = (const float*)d_in[13];
    const float* polw1 = (const float*)d_in[14];
    const float* polb1 = (const float*)d_in[15];
    const float* polw2 = (const float*)d_in[16];
    const float* polb2 = (const float*)d_in[17];
    const float* valw1 = (const float*)d_in[18];
    const float* valb1 = (const float*)d_in[19];
    const float* valw2 = (const float*)d_in[20];
    const float* valb2 = (const float*)d_in[21];
    const float* aw = (const float*)d_in[22];
    const float* ab = (const float*)d_in[23];
    const float* cw = (const float*)d_in[24];
    const float* cb = (const float*)d_in[25];

    float *Gpi, *Gvf, *Ypi, *Yvf, *Z1, *Z1b, *Z2pi, *Z2vf, *hbuf;
    cudaGetSymbolAddress((void**)&Gpi,  g_Gpi);
    cudaGetSymbolAddress((void**)&Gvf,  g_Gvf);
    cudaGetSymbolAddress((void**)&Ypi,  g_Ypi);
    cudaGetSymbolAddress((void**)&Yvf,  g_Yvf);
    cudaGetSymbolAddress((void**)&Z1,   g_Z1);
    cudaGetSymbolAddress((void**)&Z1b,  g_Z1b);
    cudaGetSymbolAddress((void**)&Z2pi, g_Z2pi);
    cudaGetSymbolAddress((void**)&Z2vf, g_Z2vf);
    cudaGetSymbolAddress((void**)&hbuf, g_hbuf);
    float* out = (float*)d_out;

    dim3 thr(256);
    // phase 1: hoisted input GEMMs  G = X @ Wih^T + bih + bhh
    sgemm_nt<<<dim3(G4 / 128, NR / 128), thr>>>(features, Wihpi, bihpi, bhhpi, Gpi, NR, G4, DD, 0);
    sgemm_nt<<<dim3(G4 / 128, NR / 128), thr>>>(features, Wihvf, bihvf, bhhvf, Gvf, NR, G4, DD, 0);

    // phase 2: persistent recurrence (both LSTMs in one grid)
    size_t shm = (size_t)(512 * 32 + 2 * 32 * 129 + 128 * 33 + 128 * 8 + 128) * sizeof(float);
    cudaFuncSetAttribute((const void*)lstm_recur,
                         cudaFuncAttributeMaxDynamicSharedMemorySize, (int)shm);
    lstm_recur<<<128, 256, shm>>>(Gpi, Gvf, starts, h0pi, c0pi, h0vf, c0vf,
                                  Whhpi, Whhvf, Ypi, Yvf, hbuf, out);

    // phase 3: MLPs (independent Z1 buffers for pi/vf)
    sgemm_nt<<<dim3(HH / 128, NR / 128), thr>>>(Ypi, polw1, polb1, nullptr, Z1,   NR, HH, HH, 1);
    sgemm_nt<<<dim3(HH / 128, NR / 128), thr>>>(Yvf, valw1, valb1, nullptr, Z1b,  NR, HH, HH, 1);
    sgemm_nt<<<dim3(HH / 128, NR / 128), thr>>>(Z1,  polw2, polb2, nullptr, Z2pi, NR, HH, HH, 0);
    sgemm_nt<<<dim3(HH / 128, NR / 128), thr>>>(Z1b, valw2, valb2, nullptr, Z2vf, NR, HH, HH, 0);

    // phase 4: heads
    head_kernel<<<NR, 128>>>(Z2pi, Z2vf, aw, ab, cw, cb, out);
}

// round 5
// speedup vs baseline: 1.3400x; 1.2813x over previous
#include <cuda_runtime.h>
#include <cuda_bf16.h>
#include <math.h>
#include <stdint.h>

// Problem constants
#define BB 128
#define TT 512
#define DD 512
#define HH 512
#define G4 2048
#define NR (BB*TT)
#define AA 32

typedef unsigned long long ull;
typedef __nv_bfloat16 bf16;

// ---------------- scratch (device globals) ----------------
__device__ float g_Gpi[(size_t)NR * G4];
__device__ float g_Gvf[(size_t)NR * G4];
__device__ float g_Ypi[(size_t)NR * HH];
__device__ float g_Yvf[(size_t)NR * HH];
__device__ float g_Z1 [(size_t)NR * HH];
__device__ float g_Z1b[(size_t)NR * HH];
__device__ float g_Z2pi[(size_t)NR * HH];
__device__ float g_Z2vf[(size_t)NR * HH];
__device__ float g_hbuf[2 * 2 * BB * HH];
__device__ unsigned g_bar_count;
__device__ unsigned g_bar_gen;

// bf16 hi/lo pairs
__device__ bf16 g_feat_h[(size_t)NR * DD];
__device__ bf16 g_feat_l[(size_t)NR * DD];
__device__ bf16 g_ypi_h[(size_t)NR * HH];
__device__ bf16 g_ypi_l[(size_t)NR * HH];
__device__ bf16 g_yvf_h[(size_t)NR * HH];
__device__ bf16 g_yvf_l[(size_t)NR * HH];
__device__ bf16 g_z1p_h[(size_t)NR * HH];
__device__ bf16 g_z1p_l[(size_t)NR * HH];
__device__ bf16 g_z1v_h[(size_t)NR * HH];
__device__ bf16 g_z1v_l[(size_t)NR * HH];
// weights blob: Wihpi Wihvf polw1 polw2 valw1 valw2
#define WOFF_IHPI 0
#define WOFF_IHVF 1048576
#define WOFF_PW1  2097152
#define WOFF_PW2  2359296
#define WOFF_VW1  2621440
#define WOFF_VW2  2883584
#define WTOT      3145728
__device__ bf16 g_w_h[WTOT];
__device__ bf16 g_w_l[WTOT];

__device__ __forceinline__ float sigf(float x) { return 1.0f / (1.0f + __expf(-x)); }

// ---------------- PTX helpers (sm_80-era only; no tcgen05 on compute_103 target) ----------------
#define CP16(d, s) asm volatile("cp.async.cg.shared.global [%0], [%1], 16;" :: "r"(d), "l"(s) : "memory")
#define CP_COMMIT() asm volatile("cp.async.commit_group;" ::: "memory")
#define CP_WAIT0()  asm volatile("cp.async.wait_group 0;" ::: "memory")
#define CP_WAIT1()  asm volatile("cp.async.wait_group 1;" ::: "memory")

__device__ __forceinline__ uint32_t smem_u32(const void* p) {
    uint32_t a;
    asm("{ .reg .u64 t; cvta.to.shared.u64 t, %1; cvt.u32.u64 %0, t; }" : "=r"(a) : "l"(p));
    return a;
}

#define MMA16816(c, a, b) \
    asm volatile("mma.sync.aligned.m16n8k16.row.col.f32.bf16.bf16.f32 " \
        "{%0,%1,%2,%3}, {%4,%5,%6,%7}, {%8,%9}, {%0,%1,%2,%3};" \
        : "+f"((c)[0]), "+f"((c)[1]), "+f"((c)[2]), "+f"((c)[3]) \
        : "r"((a)[0]), "r"((a)[1]), "r"((a)[2]), "r"((a)[3]), "r"((b)[0]), "r"((b)[1]))

// ---------------- fp32 -> bf16 hi/lo converter ----------------
__global__ __launch_bounds__(256) void cvt_pair(const float* __restrict__ x,
                                                bf16* __restrict__ hi, bf16* __restrict__ lo, size_t n4)
{
    for (size_t i = blockIdx.x * blockDim.x + threadIdx.x; i < n4; i += (size_t)gridDim.x * blockDim.x) {
        float4 v = ((const float4*)x)[i];
        bf16 h0 = __float2bfloat16_rn(v.x), h1 = __float2bfloat16_rn(v.y);
        bf16 h2 = __float2bfloat16_rn(v.z), h3 = __float2bfloat16_rn(v.w);
        bf16 l0 = __float2bfloat16_rn(v.x - __bfloat162float(h0));
        bf16 l1 = __float2bfloat16_rn(v.y - __bfloat162float(h1));
        bf16 l2 = __float2bfloat16_rn(v.z - __bfloat162float(h2));
        bf16 l3 = __float2bfloat16_rn(v.w - __bfloat162float(h3));
        __nv_bfloat162 hp0; hp0.x = h0; hp0.y = h1;
        __nv_bfloat162 hp1; hp1.x = h2; hp1.y = h3;
        __nv_bfloat162 lp0; lp0.x = l0; lp0.y = l1;
        __nv_bfloat162 lp1; lp1.x = l2; lp1.y = l3;
        ((__nv_bfloat162*)hi)[2 * i]     = hp0;
        ((__nv_bfloat162*)hi)[2 * i + 1] = hp1;
        ((__nv_bfloat162*)lo)[2 * i]     = lp0;
        ((__nv_bfloat162*)lo)[2 * i + 1] = lp1;
    }
}

// ---------------- HMMA bf16-split GEMM ----------------
// C[M,N] = A[M,512] @ W[N,512]^T (+b1+b2, opt relu), fp32 out.
// CTA 128x128 tile; 8 warps (4x2), warp tile 32x64; mma.m16n8k16 bf16->f32.
// 3-pass split: Ah*Wh + Ah*Wl + Al*Wh. Double-buffered cp.async, K-stage=32.
// smem row stride 40 bf16 (80 B) -> conflict-free fragment LDS.
#define KSTG 32
#define ROWP 40                         // padded row length in bf16
#define MATB (128 * ROWP)               // elems per matrix per stage (5120)
#define STGB (4 * MATB)                 // elems per stage (20480)
__global__ __launch_bounds__(256, 1) void tgemm(
    const bf16* __restrict__ Ah, const bf16* __restrict__ Al,
    const bf16* __restrict__ Wh, const bf16* __restrict__ Wl,
    const float* __restrict__ b1, const float* __restrict__ b2,
    float* __restrict__ C, int N, int relu)
{
    extern __shared__ bf16 smbf[];
    const int tid  = threadIdx.x;
    const int wid  = tid >> 5, lane = tid & 31;
    const int g    = lane >> 2, tig = lane & 3;
    const int m0   = (wid & 3) * 32;
    const int n0   = (wid >> 2) * 64;
    const size_t arow0 = (size_t)blockIdx.y * 128;
    const size_t brow0 = (size_t)blockIdx.x * 128;

    // loader: 4 groups of 64 threads, one matrix each; 8x 16B granules per thread
    const int lmat = tid >> 6, t64 = tid & 63;
    const bf16* gsrc;
    if      (lmat == 0) gsrc = Ah + arow0 * 512;
    else if (lmat == 1) gsrc = Al + arow0 * 512;
    else if (lmat == 2) gsrc = Wh + brow0 * 512;
    else                gsrc = Wl + brow0 * 512;
    const uint32_t sbase = smem_u32(smbf);
    const uint32_t sdstm = sbase + (uint32_t)lmat * (MATB * 2);

    float acc[2][8][4];
#pragma unroll
    for (int i = 0; i < 2; i++)
#pragma unroll
        for (int j = 0; j < 8; j++)
#pragma unroll
            for (int q = 0; q < 4; q++) acc[i][j][q] = 0.0f;

    // prologue: stages 0,1
#pragma unroll
    for (int s = 0; s < 2; s++) {
        const uint32_t db = sdstm + (uint32_t)s * (STGB * 2);
        const int k0 = s * KSTG;
#pragma unroll
        for (int i = 0; i < 8; i++) {
            int idx = i * 64 + t64;
            int row = idx >> 2, gg = idx & 3;
            CP16(db + (uint32_t)row * (ROWP * 2) + (uint32_t)gg * 16,
                 gsrc + (size_t)row * 512 + k0 + gg * 8);
        }
        CP_COMMIT();
    }

    const int NSTG = 512 / KSTG;   // 16
#pragma unroll 1
    for (int c = 0; c < NSTG; c++) {
        if (c < NSTG - 2) { CP_WAIT1(); } else { CP_WAIT0(); }
        __syncthreads();
        const bf16* S   = smbf + (size_t)(c & 1) * STGB;
        const bf16* sAh = S;
        const bf16* sAl = S + MATB;
        const bf16* sWh = S + 2 * MATB;
        const bf16* sWl = S + 3 * MATB;
#pragma unroll
        for (int kk = 0; kk < KSTG; kk += 16) {
            uint32_t ah[2][4], al[2][4];
#pragma unroll
            for (int tm = 0; tm < 2; tm++) {
                const bf16* p = sAh + (m0 + tm * 16 + g) * ROWP + kk + 2 * tig;
                ah[tm][0] = *(const uint32_t*)(p);
                ah[tm][1] = *(const uint32_t*)(p + 8 * ROWP);
                ah[tm][2] = *(const uint32_t*)(p + 8);
                ah[tm][3] = *(const uint32_t*)(p + 8 * ROWP + 8);
                const bf16* q = sAl + (m0 + tm * 16 + g) * ROWP + kk + 2 * tig;
                al[tm][0] = *(const uint32_t*)(q);
                al[tm][1] = *(const uint32_t*)(q + 8 * ROWP);
                al[tm][2] = *(const uint32_t*)(q + 8);
                al[tm][3] = *(const uint32_t*)(q + 8 * ROWP + 8);
            }
            uint32_t bh[8][2], bl[8][2];
#pragma unroll
            for (int tn = 0; tn < 8; tn++) {
                const bf16* p = sWh + (n0 + tn * 8 + g) * ROWP + kk + 2 * tig;
                bh[tn][0] = *(const uint32_t*)(p);
                bh[tn][1] = *(const uint32_t*)(p + 8);
                const bf16* q = sWl + (n0 + tn * 8 + g) * ROWP + kk + 2 * tig;
                bl[tn][0] = *(const uint32_t*)(q);
                bl[tn][1] = *(const uint32_t*)(q + 8);
            }
#pragma unroll
            for (int tm = 0; tm < 2; tm++)
#pragma unroll
                for (int tn = 0; tn < 8; tn++) {
                    MMA16816(acc[tm][tn], ah[tm], bh[tn]);
                    MMA16816(acc[tm][tn], ah[tm], bl[tn]);
                    MMA16816(acc[tm][tn], al[tm], bh[tn]);
                }
        }
        __syncthreads();
        if (c + 2 < NSTG) {
            const uint32_t db = sdstm + (uint32_t)(c & 1) * (STGB * 2);
            const int k0 = (c + 2) * KSTG;
#pragma unroll
            for (int i = 0; i < 8; i++) {
                int idx = i * 64 + t64;
                int row = idx >> 2, gg = idx & 3;
                CP16(db + (uint32_t)row * (ROWP * 2) + (uint32_t)gg * 16,
                     gsrc + (size_t)row * 512 + k0 + gg * 8);
            }
            CP_COMMIT();
        }
    }

    // epilogue: write fragments + bias (+relu)
#pragma unroll
    for (int tn = 0; tn < 8; tn++) {
        int cc = (int)brow0 + n0 + tn * 8 + 2 * tig;
        float bv0 = b1[cc]     + (b2 ? b2[cc]     : 0.0f);
        float bv1 = b1[cc + 1] + (b2 ? b2[cc + 1] : 0.0f);
#pragma unroll
        for (int tm = 0; tm < 2; tm++) {
            size_t r0 = arow0 + m0 + tm * 16 + g;
            float2 v0, v1;
            v0.x = acc[tm][tn][0] + bv0;
            v0.y = acc[tm][tn][1] + bv1;
            v1.x = acc[tm][tn][2] + bv0;
            v1.y = acc[tm][tn][3] + bv1;
            if (relu) {
                v0.x = fmaxf(v0.x, 0.f); v0.y = fmaxf(v0.y, 0.f);
                v1.x = fmaxf(v1.x, 0.f); v1.y = fmaxf(v1.y, 0.f);
            }
            *(float2*)(C + r0 * (size_t)N + cc)       = v0;
            *(float2*)(C + (r0 + 8) * (size_t)N + cc) = v1;
        }
    }
}

// ---------------- software grid barrier ----------------
__device__ __forceinline__ void grid_bar(int nct) {
    __syncthreads();
    if (threadIdx.x == 0) {
        __threadfence();
        volatile unsigned* vgen = &g_bar_gen;
        unsigned g = *vgen;
        unsigned a = atomicAdd(&g_bar_count, 1u);
        if (a == (unsigned)nct - 1u) {
            g_bar_count = 0u;
            __threadfence();
            atomicAdd(&g_bar_gen, 1u);
        } else {
            while (*vgen == g) { }
        }
        __threadfence();
    }
    __syncthreads();
}

// ---------------- persistent recurrent kernel (fp32, as R2/R3) ----------------
__global__ __launch_bounds__(256, 1) void lstm_recur(
    const float* __restrict__ Gpi, const float* __restrict__ Gvf,
    const float* __restrict__ starts,
    const float* __restrict__ h0pi, const float* __restrict__ c0pi,
    const float* __restrict__ h0vf, const float* __restrict__ c0vf,
    const float* __restrict__ Whhpi, const float* __restrict__ Whhvf,
    float* __restrict__ Ypi, float* __restrict__ Yvf,
    float* __restrict__ hbuf, float* __restrict__ out)
{
    extern __shared__ float smemf[];
    float* sW  = smemf;
    float* sh0 = sW + 512 * 32;
    float* sh1 = sh0 + 32 * 129;
    float* sg  = sh1 + 32 * 129;
    float* sc  = sg + 128 * 33;
    float* sm  = sc + 128 * 8;

    const int ct   = blockIdx.x;
    const int lstm = ct >> 6;
    const int cid  = ct & 63;
    const int hc0  = cid * 8;
    const int tx   = threadIdx.x;
    const int trow = tx >> 3;
    const int tcol = tx & 7;

    const float* Gx  = lstm ? Gvf   : Gpi;
    const float* Whh = lstm ? Whhvf : Whhpi;
    const float* h0  = lstm ? h0vf  : h0pi;
    const float* c0  = lstm ? c0vf  : c0pi;
    float* Y  = lstm ? Yvf : Ypi;
    float* hb = hbuf + lstm * 2 * BB * HH;

    int stb[4], stk[4];
#pragma unroll
    for (int r = 0; r < 4; r++) {
        int f4 = tx + r * 256;
        stb[r] = f4 >> 3;
        stk[r] = (f4 & 7) << 2;
    }

    for (int idx = tx; idx < 32 * 512; idx += 256) {
        int j = idx >> 9;
        int k = idx & 511;
        int gc = ((j >> 3) << 9) + hc0 + (j & 7);
        sW[k * 32 + j] = Whh[(size_t)gc * HH + k];
    }
    for (int idx = tx; idx < BB * 8; idx += 256) {
        int b = idx >> 3, q = idx & 7;
        hb[b * HH + hc0 + q] = h0[b * HH + hc0 + q];
        sc[b * 8 + q]        = c0[b * HH + hc0 + q];
    }
    __threadfence();
    grid_bar(gridDim.x);

    for (int t = 0; t < TT; t++) {
        const int cur = t & 1, nxt = cur ^ 1;
        const float* hc = hb + cur * BB * HH;

        float4 pre[4];
#pragma unroll
        for (int r = 0; r < 4; r++)
            pre[r] = *(const float4*)(hc + stb[r] * HH + stk[r]);
        if (tx < BB) sm[tx] = 1.0f - starts[tx * TT + t];
        __syncthreads();
#pragma unroll
        for (int r = 0; r < 4; r++) {
            float m = sm[stb[r]];
            sh0[(stk[r] + 0) * 129 + stb[r]] = pre[r].x * m;
            sh0[(stk[r] + 1) * 129 + stb[r]] = pre[r].y * m;
            sh0[(stk[r] + 2) * 129 + stb[r]] = pre[r].z * m;
            sh0[(stk[r] + 3) * 129 + stb[r]] = pre[r].w * m;
        }
        __syncthreads();

        float acc[4][4];
#pragma unroll
        for (int i = 0; i < 4; i++)
#pragma unroll
            for (int j = 0; j < 4; j++) acc[i][j] = 0.0f;

#pragma unroll 1
        for (int c = 0; c < 16; c++) {
            const int k0 = c << 5;
            if (c < 15) {
#pragma unroll
                for (int r = 0; r < 4; r++)
                    pre[r] = *(const float4*)(hc + stb[r] * HH + k0 + 32 + stk[r]);
            }
            const float* shc = (c & 1) ? sh1 : sh0;
#pragma unroll
            for (int kk = 0; kk < 32; kk++) {
                float4 w4 = *(const float4*)&sW[(k0 + kk) * 32 + tcol * 4];
                float h0v = shc[kk * 129 + trow * 4 + 0];
                float h1v = shc[kk * 129 + trow * 4 + 1];
                float h2v = shc[kk * 129 + trow * 4 + 2];
                float h3v = shc[kk * 129 + trow * 4 + 3];
                acc[0][0] += h0v * w4.x; acc[0][1] += h0v * w4.y; acc[0][2] += h0v * w4.z; acc[0][3] += h0v * w4.w;
                acc[1][0] += h1v * w4.x; acc[1][1] += h1v * w4.y; acc[1][2] += h1v * w4.z; acc[1][3] += h1v * w4.w;
                acc[2][0] += h2v * w4.x; acc[2][1] += h2v * w4.y; acc[2][2] += h2v * w4.z; acc[2][3] += h2v * w4.w;
                acc[3][0] += h3v * w4.x; acc[3][1] += h3v * w4.y; acc[3][2] += h3v * w4.z; acc[3][3] += h3v * w4.w;
            }
            if (c < 15) {
                float* shn = (c & 1) ? sh0 : sh1;
#pragma unroll
                for (int r = 0; r < 4; r++) {
                    float m = sm[stb[r]];
                    shn[(stk[r] + 0) * 129 + stb[r]] = pre[r].x * m;
                    shn[(stk[r] + 1) * 129 + stb[r]] = pre[r].y * m;
                    shn[(stk[r] + 2) * 129 + stb[r]] = pre[r].z * m;
                    shn[(stk[r] + 3) * 129 + stb[r]] = pre[r].w * m;
                }
            }
            __syncthreads();
        }

        {
            int gcb = ((tcol >> 1) << 9) + hc0 + ((tcol & 1) << 2);
#pragma unroll
            for (int i = 0; i < 4; i++) {
                int b = trow * 4 + i;
                float4 gx = *(const float4*)(Gx + (size_t)(b * TT + t) * G4 + gcb);
                sg[b * 33 + tcol * 4 + 0] = acc[i][0] + gx.x;
                sg[b * 33 + tcol * 4 + 1] = acc[i][1] + gx.y;
                sg[b * 33 + tcol * 4 + 2] = acc[i][2] + gx.z;
                sg[b * 33 + tcol * 4 + 3] = acc[i][3] + gx.w;
            }
        }
        __syncthreads();

        {
            int b  = tx >> 1;
            int kb = (tx & 1) << 2;
            float m = sm[b];
            float hout[4];
#pragma unroll
            for (int i = 0; i < 4; i++) {
                int kk = kb + i;
                float gi = sg[b * 33 + kk];
                float gf = sg[b * 33 + 8 + kk];
                float gz = sg[b * 33 + 16 + kk];
                float go = sg[b * 33 + 24 + kk];
                float cc = sc[b * 8 + kk] * m;
                float cn = sigf(gf) * cc + sigf(gi) * tanhf(gz);
                float hn = sigf(go) * tanhf(cn);
                sc[b * 8 + kk] = cn;
                hout[i] = hn;
            }
            float4 hv = make_float4(hout[0], hout[1], hout[2], hout[3]);
            *(float4*)(hb + nxt * BB * HH + b * HH + hc0 + kb) = hv;
            *(float4*)(Y + (size_t)(b * TT + t) * HH + hc0 + kb) = hv;
        }
        __threadfence();
        grid_bar(gridDim.x);
    }

    float* oh = out + (size_t)3 * NR + (size_t)lstm * 2 * NR;
    float* oc = oh + NR;
    for (int idx = tx; idx < BB * 8; idx += 256) {
        int b = idx >> 3, q = idx & 7;
        oh[b * HH + hc0 + q] = hb[0 * BB * HH + b * HH + hc0 + q];
        oc[b * HH + hc0 + q] = sc[b * 8 + q];
    }
}

// ---------------- heads ----------------
__global__ __launch_bounds__(128) void head_kernel(
    const float* __restrict__ Zpi, const float* __restrict__ Zvf,
    const float* __restrict__ aw, const float* __restrict__ ab,
    const float* __restrict__ cw, const float* __restrict__ cb,
    float* __restrict__ out)
{
    __shared__ float sx[512];
    __shared__ float slog[32];
    __shared__ float sval[4];
    const int n  = blockIdx.x;
    const int tx = threadIdx.x;

    ((float4*)sx)[tx] = ((const float4*)(Zpi + (size_t)n * 512))[tx];

    float4 xv = ((const float4*)(Zvf + (size_t)n * 512))[tx];
    float4 wv = ((const float4*)cw)[tx];
    float v = xv.x * wv.x + xv.y * wv.y + xv.z * wv.z + xv.w * wv.w;
#pragma unroll
    for (int off = 16; off; off >>= 1) v += __shfl_xor_sync(0xffffffffu, v, off);
    if ((tx & 31) == 0) sval[tx >> 5] = v;
    __syncthreads();

    const int l = tx >> 2;
    const int part = tx & 3;
    const float* wl = aw + l * 512 + part * 128;
    const float* xl = sx + part * 128;
    float s = 0.0f;
#pragma unroll 8
    for (int k4 = 0; k4 < 32; k4++) {
        float4 a = ((const float4*)xl)[k4];
        float4 w = ((const float4*)wl)[k4];
        s += a.x * w.x + a.y * w.y + a.z * w.z + a.w * w.w;
    }
    s += __shfl_xor_sync(0xffffffffu, s, 1);
    s += __shfl_xor_sync(0xffffffffu, s, 2);
    if (part == 0) slog[l] = s + ab[l];
    __syncthreads();

    if (tx < 32) {
        float lv = slog[tx];
        float m = lv; int mi = tx;
#pragma unroll
        for (int off = 16; off; off >>= 1) {
            float om = __shfl_xor_sync(0xffffffffu, m, off);
            int   oi = __shfl_xor_sync(0xffffffffu, mi, off);
            if (om > m || (om == m && oi < mi)) { m = om; mi = oi; }
        }
        float e = __expf(lv - m);
#pragma unroll
        for (int off = 16; off; off >>= 1) e += __shfl_xor_sync(0xffffffffu, e, off);
        if (tx == 0) {
            out[n] = (float)mi;
            out[(size_t)NR + n] = sval[0] + sval[1] + sval[2] + sval[3] + cb[0];
            out[(size_t)2 * NR + n] = -__logf(e);
        }
    }
}

// ---------------- launch ----------------
extern "C" void kernel_launch(void* const* d_in, const int* in_sizes, int n_in,
                              void* d_out, int out_size)
{
    const float* features = (const float*)d_in[0];
    const float* starts   = (const float*)d_in[1];
    const float* h0pi = (const float*)d_in[2];
    const float* c0pi = (const float*)d_in[3];
    const float* h0vf = (const float*)d_in[4];
    const float* c0vf = (const float*)d_in[5];
    const float* Wihpi = (const float*)d_in[6];
    const float* Whhpi = (const float*)d_in[7];
    const float* bihpi = (const float*)d_in[8];
    const float* bhhpi = (const float*)d_in[9];
    const float* Wihvf = (const float*)d_in[10];
    const float* Whhvf = (const float*)d_in[11];
    const float* bihvf = (const float*)d_in[12];
    const float* bhhvf = (const float*)d_in[13];
    const float* polw1 = (const float*)d_in[14];
    const float* polb1 = (const float*)d_in[15];
    const float* polw2 = (const float*)d_in[16];
    const float* polb2 = (const float*)d_in[17];
    const float* valw1 = (const float*)d_in[18];
    const float* valb1 = (const float*)d_in[19];
    const float* valw2 = (const float*)d_in[20];
    const float* valb2 = (const float*)d_in[21];
    const float* aw = (const float*)d_in[22];
    const float* ab = (const float*)d_in[23];
    const float* cw = (const float*)d_in[24];
    const float* cb = (const float*)d_in[25];

    float *Gpi, *Gvf, *Ypi, *Yvf, *Z1, *Z1b, *Z2pi, *Z2vf, *hbuf;
    cudaGetSymbolAddress((void**)&Gpi,  g_Gpi);
    cudaGetSymbolAddress((void**)&Gvf,  g_Gvf);
    cudaGetSymbolAddress((void**)&Ypi,  g_Ypi);
    cudaGetSymbolAddress((void**)&Yvf,  g_Yvf);
    cudaGetSymbolAddress((void**)&Z1,   g_Z1);
    cudaGetSymbolAddress((void**)&Z1b,  g_Z1b);
    cudaGetSymbolAddress((void**)&Z2pi, g_Z2pi);
    cudaGetSymbolAddress((void**)&Z2vf, g_Z2vf);
    cudaGetSymbolAddress((void**)&hbuf, g_hbuf);
    bf16 *fh, *fl, *yph, *ypl, *yvh, *yvl, *z1ph, *z1pl, *z1vh, *z1vl, *wh, *wlp;
    cudaGetSymbolAddress((void**)&fh,  g_feat_h);
    cudaGetSymbolAddress((void**)&fl,  g_feat_l);
    cudaGetSymbolAddress((void**)&yph, g_ypi_h);
    cudaGetSymbolAddress((void**)&ypl, g_ypi_l);
    cudaGetSymbolAddress((void**)&yvh, g_yvf_h);
    cudaGetSymbolAddress((void**)&yvl, g_yvf_l);
    cudaGetSymbolAddress((void**)&z1ph, g_z1p_h);
    cudaGetSymbolAddress((void**)&z1pl, g_z1p_l);
    cudaGetSymbolAddress((void**)&z1vh, g_z1v_h);
    cudaGetSymbolAddress((void**)&z1vl, g_z1v_l);
    cudaGetSymbolAddress((void**)&wh,  g_w_h);
    cudaGetSymbolAddress((void**)&wlp, g_w_l);
    float* out = (float*)d_out;

    size_t tg_smem = (size_t)2 * STGB * sizeof(bf16);   // 81920
    size_t rc_smem = (size_t)(512 * 32 + 2 * 32 * 129 + 128 * 33 + 128 * 8 + 128) * sizeof(float);
    cudaFuncSetAttribute((const void*)tgemm, cudaFuncAttributeMaxDynamicSharedMemorySize, (int)tg_smem);
    cudaFuncSetAttribute((const void*)lstm_recur, cudaFuncAttributeMaxDynamicSharedMemorySize, (int)rc_smem);

    // converts: features + weights
    cvt_pair<<<2048, 256>>>(features, fh, fl, (size_t)NR * DD / 4);
    cvt_pair<<<256, 256>>>(Wihpi, wh + WOFF_IHPI, wlp + WOFF_IHPI, (size_t)G4 * DD / 4);
    cvt_pair<<<256, 256>>>(Wihvf, wh + WOFF_IHVF, wlp + WOFF_IHVF, (size_t)G4 * DD / 4);
    cvt_pair<<<128, 256>>>(polw1, wh + WOFF_PW1, wlp + WOFF_PW1, (size_t)HH * HH / 4);
    cvt_pair<<<128, 256>>>(polw2, wh + WOFF_PW2, wlp + WOFF_PW2, (size_t)HH * HH / 4);
    cvt_pair<<<128, 256>>>(valw1, wh + WOFF_VW1, wlp + WOFF_VW1, (size_t)HH * HH / 4);
    cvt_pair<<<128, 256>>>(valw2, wh + WOFF_VW2, wlp + WOFF_VW2, (size_t)HH * HH / 4);

    // input GEMMs: G = X @ Wih^T + bih + bhh
    tgemm<<<dim3(G4 / 128, NR / 128), 256, tg_smem>>>(fh, fl, wh + WOFF_IHPI, wlp + WOFF_IHPI,
                                                      bihpi, bhhpi, Gpi, G4, 0);
    tgemm<<<dim3(G4 / 128, NR / 128), 256, tg_smem>>>(fh, fl, wh + WOFF_IHVF, wlp + WOFF_IHVF,
                                                      bihvf, bhhvf, Gvf, G4, 0);

    // recurrence
    lstm_recur<<<128, 256, rc_smem>>>(Gpi, Gvf, starts, h0pi, c0pi, h0vf, c0vf,
                                      Whhpi, Whhvf, Ypi, Yvf, hbuf, out);

    // MLP layer 1
    cvt_pair<<<2048, 256>>>(Ypi, yph, ypl, (size_t)NR * HH / 4);
    cvt_pair<<<2048, 256>>>(Yvf, yvh, yvl, (size_t)NR * HH / 4);
    tgemm<<<dim3(HH / 128, NR / 128), 256, tg_smem>>>(yph, ypl, wh + WOFF_PW1, wlp + WOFF_PW1,
                                                      polb1, nullptr, Z1, HH, 1);
    tgemm<<<dim3(HH / 128, NR / 128), 256, tg_smem>>>(yvh, yvl, wh + WOFF_VW1, wlp + WOFF_VW1,
                                                      valb1, nullptr, Z1b, HH, 1);

    // MLP layer 2
    cvt_pair<<<2048, 256>>>(Z1,  z1ph, z1pl, (size_t)NR * HH / 4);
    cvt_pair<<<2048, 256>>>(Z1b, z1vh, z1vl, (size_t)NR * HH / 4);
    tgemm<<<dim3(HH / 128, NR / 128), 256, tg_smem>>>(z1ph, z1pl, wh + WOFF_PW2, wlp + WOFF_PW2,
                                                      polb2, nullptr, Z2pi, HH, 0);
    tgemm<<<dim3(HH / 128, NR / 128), 256, tg_smem>>>(z1vh, z1vl, wh + WOFF_VW2, wlp + WOFF_VW2,
                                                      valb2, nullptr, Z2vf, HH, 0);

    // heads
    head_kernel<<<NR, 128>>>(Z2pi, Z2vf, aw, ab, cw, cb, out);
}

// round 6
// speedup vs baseline: 1.8322x; 1.3673x over previous
#include <cuda_runtime.h>
#include <cuda_bf16.h>
#include <math.h>
#include <stdint.h>

// Problem constants
#define BB 128
#define TT 512
#define DD 512
#define HH 512
#define G4 2048
#define NR (BB*TT)
#define AA 32

typedef __nv_bfloat16 bf16;

// ---------------- scratch (device globals) ----------------
__device__ float g_Gpi[(size_t)NR * G4];
__device__ float g_Gvf[(size_t)NR * G4];
__device__ float g_Z2pi[(size_t)NR * HH];
__device__ float g_Z2vf[(size_t)NR * HH];
__device__ unsigned g_bar_count;
__device__ unsigned g_bar_gen;

// bf16 hi/lo pairs
__device__ __align__(16) bf16 g_feat_h[(size_t)NR * DD];
__device__ __align__(16) bf16 g_feat_l[(size_t)NR * DD];
__device__ __align__(16) bf16 g_ypi_h[(size_t)NR * HH];
__device__ __align__(16) bf16 g_ypi_l[(size_t)NR * HH];
__device__ __align__(16) bf16 g_yvf_h[(size_t)NR * HH];
__device__ __align__(16) bf16 g_yvf_l[(size_t)NR * HH];
__device__ __align__(16) bf16 g_z1p_h[(size_t)NR * HH];
__device__ __align__(16) bf16 g_z1p_l[(size_t)NR * HH];
__device__ __align__(16) bf16 g_z1v_h[(size_t)NR * HH];
__device__ __align__(16) bf16 g_z1v_l[(size_t)NR * HH];
// h ping-pong: [lstm][pingpong][128][512], bf16 hi/lo (pre-masked for the consuming step)
__device__ __align__(16) bf16 g_hh[2 * 2 * BB * HH];
__device__ __align__(16) bf16 g_hl[2 * 2 * BB * HH];
// weights blob: Wihpi Wihvf polw1 polw2 valw1 valw2
#define WOFF_IHPI 0
#define WOFF_IHVF 1048576
#define WOFF_PW1  2097152
#define WOFF_PW2  2359296
#define WOFF_VW1  2621440
#define WOFF_VW2  2883584
#define WTOT      3145728
__device__ __align__(16) bf16 g_w_h[WTOT];
__device__ __align__(16) bf16 g_w_l[WTOT];

__device__ __forceinline__ float sigf(float x) { return 1.0f / (1.0f + __expf(-x)); }

// ---------------- PTX helpers ----------------
#define CP16(d, s) asm volatile("cp.async.cg.shared.global [%0], [%1], 16;" :: "r"(d), "l"(s) : "memory")
#define CP_COMMIT() asm volatile("cp.async.commit_group;" ::: "memory")
#define CP_WAIT0()  asm volatile("cp.async.wait_group 0;" ::: "memory")
#define CP_WAIT1()  asm volatile("cp.async.wait_group 1;" ::: "memory")

__device__ __forceinline__ uint32_t smem_u32(const void* p) {
    uint32_t a;
    asm("{ .reg .u64 t; cvta.to.shared.u64 t, %1; cvt.u32.u64 %0, t; }" : "=r"(a) : "l"(p));
    return a;
}

#define MMA16816(c, a, b) \
    asm volatile("mma.sync.aligned.m16n8k16.row.col.f32.bf16.bf16.f32 " \
        "{%0,%1,%2,%3}, {%4,%5,%6,%7}, {%8,%9}, {%0,%1,%2,%3};" \
        : "+f"((c)[0]), "+f"((c)[1]), "+f"((c)[2]), "+f"((c)[3]) \
        : "r"((a)[0]), "r"((a)[1]), "r"((a)[2]), "r"((a)[3]), "r"((b)[0]), "r"((b)[1]))

// ---------------- fp32 -> bf16 hi/lo converter ----------------
__global__ __launch_bounds__(256) void cvt_pair(const float* __restrict__ x,
                                                bf16* __restrict__ hi, bf16* __restrict__ lo, size_t n4)
{
    for (size_t i = blockIdx.x * blockDim.x + threadIdx.x; i < n4; i += (size_t)gridDim.x * blockDim.x) {
        float4 v = ((const float4*)x)[i];
        bf16 h0 = __float2bfloat16_rn(v.x), h1 = __float2bfloat16_rn(v.y);
        bf16 h2 = __float2bfloat16_rn(v.z), h3 = __float2bfloat16_rn(v.w);
        bf16 l0 = __float2bfloat16_rn(v.x - __bfloat162float(h0));
        bf16 l1 = __float2bfloat16_rn(v.y - __bfloat162float(h1));
        bf16 l2 = __float2bfloat16_rn(v.z - __bfloat162float(h2));
        bf16 l3 = __float2bfloat16_rn(v.w - __bfloat162float(h3));
        __nv_bfloat162 hp0; hp0.x = h0; hp0.y = h1;
        __nv_bfloat162 hp1; hp1.x = h2; hp1.y = h3;
        __nv_bfloat162 lp0; lp0.x = l0; lp0.y = l1;
        __nv_bfloat162 lp1; lp1.x = l2; lp1.y = l3;
        ((__nv_bfloat162*)hi)[2 * i]     = hp0;
        ((__nv_bfloat162*)hi)[2 * i + 1] = hp1;
        ((__nv_bfloat162*)lo)[2 * i]     = lp0;
        ((__nv_bfloat162*)lo)[2 * i + 1] = lp1;
    }
}

// ---------------- HMMA bf16-split GEMM (R4, + optional bf16-split output) ----------------
#define KSTG 32
#define ROWP 40
#define MATB (128 * ROWP)
#define STGB (4 * MATB)
__global__ __launch_bounds__(256, 1) void tgemm(
    const bf16* __restrict__ Ah, const bf16* __restrict__ Al,
    const bf16* __restrict__ Wh, const bf16* __restrict__ Wl,
    const float* __restrict__ b1, const float* __restrict__ b2,
    float* __restrict__ C, bf16* __restrict__ Ch, bf16* __restrict__ Cl,
    int N, int relu)
{
    extern __shared__ bf16 smbf[];
    const int tid  = threadIdx.x;
    const int wid  = tid >> 5, lane = tid & 31;
    const int g    = lane >> 2, tig = lane & 3;
    const int m0   = (wid & 3) * 32;
    const int n0   = (wid >> 2) * 64;
    const size_t arow0 = (size_t)blockIdx.y * 128;
    const size_t brow0 = (size_t)blockIdx.x * 128;

    const int lmat = tid >> 6, t64 = tid & 63;
    const bf16* gsrc;
    if      (lmat == 0) gsrc = Ah + arow0 * 512;
    else if (lmat == 1) gsrc = Al + arow0 * 512;
    else if (lmat == 2) gsrc = Wh + brow0 * 512;
    else                gsrc = Wl + brow0 * 512;
    const uint32_t sbase = smem_u32(smbf);
    const uint32_t sdstm = sbase + (uint32_t)lmat * (MATB * 2);

    float acc[2][8][4];
#pragma unroll
    for (int i = 0; i < 2; i++)
#pragma unroll
        for (int j = 0; j < 8; j++)
#pragma unroll
            for (int q = 0; q < 4; q++) acc[i][j][q] = 0.0f;

#pragma unroll
    for (int s = 0; s < 2; s++) {
        const uint32_t db = sdstm + (uint32_t)s * (STGB * 2);
        const int k0 = s * KSTG;
#pragma unroll
        for (int i = 0; i < 8; i++) {
            int idx = i * 64 + t64;
            int row = idx >> 2, gg = idx & 3;
            CP16(db + (uint32_t)row * (ROWP * 2) + (uint32_t)gg * 16,
                 gsrc + (size_t)row * 512 + k0 + gg * 8);
        }
        CP_COMMIT();
    }

    const int NSTG = 512 / KSTG;
#pragma unroll 1
    for (int c = 0; c < NSTG; c++) {
        if (c < NSTG - 2) { CP_WAIT1(); } else { CP_WAIT0(); }
        __syncthreads();
        const bf16* S   = smbf + (size_t)(c & 1) * STGB;
        const bf16* sAh = S;
        const bf16* sAl = S + MATB;
        const bf16* sWh = S + 2 * MATB;
        const bf16* sWl = S + 3 * MATB;
#pragma unroll
        for (int kk = 0; kk < KSTG; kk += 16) {
            uint32_t ah[2][4], al[2][4];
#pragma unroll
            for (int tm = 0; tm < 2; tm++) {
                const bf16* p = sAh + (m0 + tm * 16 + g) * ROWP + kk + 2 * tig;
                ah[tm][0] = *(const uint32_t*)(p);
                ah[tm][1] = *(const uint32_t*)(p + 8 * ROWP);
                ah[tm][2] = *(const uint32_t*)(p + 8);
                ah[tm][3] = *(const uint32_t*)(p + 8 * ROWP + 8);
                const bf16* q = sAl + (m0 + tm * 16 + g) * ROWP + kk + 2 * tig;
                al[tm][0] = *(const uint32_t*)(q);
                al[tm][1] = *(const uint32_t*)(q + 8 * ROWP);
                al[tm][2] = *(const uint32_t*)(q + 8);
                al[tm][3] = *(const uint32_t*)(q + 8 * ROWP + 8);
            }
            uint32_t bh[8][2], bl[8][2];
#pragma unroll
            for (int tn = 0; tn < 8; tn++) {
                const bf16* p = sWh + (n0 + tn * 8 + g) * ROWP + kk + 2 * tig;
                bh[tn][0] = *(const uint32_t*)(p);
                bh[tn][1] = *(const uint32_t*)(p + 8);
                const bf16* q = sWl + (n0 + tn * 8 + g) * ROWP + kk + 2 * tig;
                bl[tn][0] = *(const uint32_t*)(q);
                bl[tn][1] = *(const uint32_t*)(q + 8);
            }
#pragma unroll
            for (int tm = 0; tm < 2; tm++)
#pragma unroll
                for (int tn = 0; tn < 8; tn++) {
                    MMA16816(acc[tm][tn], ah[tm], bh[tn]);
                    MMA16816(acc[tm][tn], ah[tm], bl[tn]);
                    MMA16816(acc[tm][tn], al[tm], bh[tn]);
                }
        }
        __syncthreads();
        if (c + 2 < NSTG) {
            const uint32_t db = sdstm + (uint32_t)(c & 1) * (STGB * 2);
            const int k0 = (c + 2) * KSTG;
#pragma unroll
            for (int i = 0; i < 8; i++) {
                int idx = i * 64 + t64;
                int row = idx >> 2, gg = idx & 3;
                CP16(db + (uint32_t)row * (ROWP * 2) + (uint32_t)gg * 16,
                     gsrc + (size_t)row * 512 + k0 + gg * 8);
            }
            CP_COMMIT();
        }
    }

#pragma unroll
    for (int tn = 0; tn < 8; tn++) {
        int cc = (int)brow0 + n0 + tn * 8 + 2 * tig;
        float bv0 = b1[cc]     + (b2 ? b2[cc]     : 0.0f);
        float bv1 = b1[cc + 1] + (b2 ? b2[cc + 1] : 0.0f);
#pragma unroll
        for (int tm = 0; tm < 2; tm++) {
            size_t r0 = arow0 + m0 + tm * 16 + g;
            float v[4];
            v[0] = acc[tm][tn][0] + bv0;
            v[1] = acc[tm][tn][1] + bv1;
            v[2] = acc[tm][tn][2] + bv0;
            v[3] = acc[tm][tn][3] + bv1;
            if (relu) {
#pragma unroll
                for (int q = 0; q < 4; q++) v[q] = fmaxf(v[q], 0.f);
            }
            if (Ch) {
                __nv_bfloat162 h0, h1, l0, l1;
                h0.x = __float2bfloat16_rn(v[0]); h0.y = __float2bfloat16_rn(v[1]);
                h1.x = __float2bfloat16_rn(v[2]); h1.y = __float2bfloat16_rn(v[3]);
                l0.x = __float2bfloat16_rn(v[0] - __bfloat162float(h0.x));
                l0.y = __float2bfloat16_rn(v[1] - __bfloat162float(h0.y));
                l1.x = __float2bfloat16_rn(v[2] - __bfloat162float(h1.x));
                l1.y = __float2bfloat16_rn(v[3] - __bfloat162float(h1.y));
                *(__nv_bfloat162*)(Ch + r0 * (size_t)N + cc)       = h0;
                *(__nv_bfloat162*)(Cl + r0 * (size_t)N + cc)       = l0;
                *(__nv_bfloat162*)(Ch + (r0 + 8) * (size_t)N + cc) = h1;
                *(__nv_bfloat162*)(Cl + (r0 + 8) * (size_t)N + cc) = l1;
            } else {
                *(float2*)(C + r0 * (size_t)N + cc)       = make_float2(v[0], v[1]);
                *(float2*)(C + (r0 + 8) * (size_t)N + cc) = make_float2(v[2], v[3]);
            }
        }
    }
}

// ---------------- software grid barrier ----------------
__device__ __forceinline__ void grid_bar(int nct) {
    __threadfence();
    __syncthreads();
    if (threadIdx.x == 0) {
        volatile unsigned* vgen = &g_bar_gen;
        unsigned g = *vgen;
        unsigned a = atomicAdd(&g_bar_count, 1u);
        if (a == (unsigned)nct - 1u) {
            g_bar_count = 0u;
            __threadfence();
            atomicAdd(&g_bar_gen, 1u);
        } else {
            while (*vgen == g) { }
        }
        __threadfence();
    }
    __syncthreads();
}

// ---------------- persistent recurrent kernel: HMMA bf16-split ----------------
// 128 CTAs x 256 thr. CTA ct: lstm = ct>>6, owns 8 h-cols hc0=(ct&63)*8 (32 gate cols).
// Per step: gates[128,32] = h[128,512] @ WhhT_slice[512,32] via m16n8k16, 3-pass split.
// h stored bf16 hi/lo PRE-MASKED for the consuming step; staged via cp.async.
#define RPAD 72
#define WPAD 520
#define SGPAD 40
#define OFF_WH   0
#define OFF_WL   (32 * WPAD * 2)
#define OFF_HH0  (2 * 32 * WPAD * 2)
#define OFF_HH1  (OFF_HH0 + 128 * RPAD * 2)
#define OFF_HL0  (OFF_HH0 + 2 * 128 * RPAD * 2)
#define OFF_HL1  (OFF_HL0 + 128 * RPAD * 2)
#define OFF_SG   (OFF_HH0 + 4 * 128 * RPAD * 2)
#define OFF_MASK (OFF_SG + 128 * SGPAD * 4)
#define OFF_SC   (OFF_MASK + 256 * 4)
#define LSTM_SMEM (OFF_SC + 128 * 8 * 4)

__global__ __launch_bounds__(256, 1) void lstm_recur(
    const float* __restrict__ Gpi, const float* __restrict__ Gvf,
    const float* __restrict__ starts,
    const float* __restrict__ h0pi, const float* __restrict__ c0pi,
    const float* __restrict__ h0vf, const float* __restrict__ c0vf,
    const float* __restrict__ Whhpi, const float* __restrict__ Whhvf,
    bf16* __restrict__ Yph, bf16* __restrict__ Ypl,
    bf16* __restrict__ Yvh, bf16* __restrict__ Yvl,
    bf16* __restrict__ hhg, bf16* __restrict__ hlg,
    float* __restrict__ out)
{
    extern __shared__ char sm8[];
    bf16*  sWh = (bf16*)(sm8 + OFF_WH);
    bf16*  sWl = (bf16*)(sm8 + OFF_WL);
    float* sg  = (float*)(sm8 + OFF_SG);
    float* smk = (float*)(sm8 + OFF_MASK);
    float* sc  = (float*)(sm8 + OFF_SC);

    const int ct   = blockIdx.x;
    const int lstm = ct >> 6;
    const int cid  = ct & 63;
    const int hc0  = cid * 8;
    const int tx   = threadIdx.x;
    const int wid  = tx >> 5, lane = tx & 31;
    const int g    = lane >> 2, tig = lane & 3;
    const int m0w  = (wid & 3) * 32;
    const int wc   = wid >> 2;

    const float* Gx  = lstm ? Gvf   : Gpi;
    const float* Whh = lstm ? Whhvf : Whhpi;
    const float* h0  = lstm ? h0vf  : h0pi;
    const float* c0  = lstm ? c0vf  : c0pi;
    bf16* Yh = lstm ? Yvh : Yph;
    bf16* Yl = lstm ? Yvl : Ypl;
    bf16* hhb = hhg + lstm * 2 * BB * HH;
    bf16* hlb = hlg + lstm * 2 * BB * HH;

    const uint32_t sb = smem_u32(sm8);
    const uint32_t shh[2] = { sb + OFF_HH0, sb + OFF_HH1 };
    const uint32_t shl[2] = { sb + OFF_HL0, sb + OFF_HL1 };

    // load + split Whh slice: sW[j][k], j = gate*8 + q (packed 32 cols)
    for (int s = 0; s < 64; s++) {
        int idx = tx + s * 256;
        int j = idx >> 9, k = idx & 511;
        int gc = ((j >> 3) << 9) + hc0 + (j & 7);
        float w = Whh[(size_t)gc * HH + k];
        bf16 hi = __float2bfloat16_rn(w);
        sWh[j * WPAD + k] = hi;
        sWl[j * WPAD + k] = __float2bfloat16_rn(w - __bfloat162float(hi));
    }
    // init c (smem) and h0 (ping 0, pre-masked with m0, bf16 split)
    for (int s = 0; s < 4; s++) {
        int idx = tx + s * 256;
        int b = idx >> 3, q = idx & 7;
        sc[b * 8 + q] = c0[b * HH + hc0 + q];
        float m0 = 1.0f - starts[b * TT];
        float v = h0[b * HH + hc0 + q] * m0;
        bf16 hi = __float2bfloat16_rn(v);
        hhb[b * HH + hc0 + q] = hi;
        hlb[b * HH + hc0 + q] = __float2bfloat16_rn(v - __bfloat162float(hi));
    }
    grid_bar(gridDim.x);

    for (int t = 0; t < TT; t++) {
        const int cur = t & 1;
        const bf16* hcH = hhb + cur * BB * HH;
        const bf16* hcL = hlb + cur * BB * HH;

        // prefetch chunk 0 (K 0..63)
        {
#pragma unroll
            for (int i = 0; i < 4; i++) {
                int idx = tx + i * 256;
                int row = idx >> 3, gg = idx & 7;
                uint32_t so = (uint32_t)row * (RPAD * 2) + (uint32_t)gg * 16;
                size_t  go = (size_t)row * 512 + gg * 8;
                CP16(shh[0] + so, hcH + go);
                CP16(shl[0] + so, hcL + go);
            }
            CP_COMMIT();
        }
        // masks
        if (tx < 128) smk[tx] = 1.0f - starts[tx * TT + t];
        else {
            int b = tx - 128;
            smk[128 + b] = (t + 1 < TT) ? (1.0f - starts[b * TT + t + 1]) : 1.0f;
        }

        float acc[2][2][4];
#pragma unroll
        for (int tm = 0; tm < 2; tm++)
#pragma unroll
            for (int tn = 0; tn < 2; tn++)
#pragma unroll
                for (int q = 0; q < 4; q++) acc[tm][tn][q] = 0.0f;

#pragma unroll 1
        for (int c = 0; c < 8; c++) {
            const int buf = c & 1;
            if (c < 7) {
                const int nb = buf ^ 1;
                const int kc = (c + 1) * 64;
#pragma unroll
                for (int i = 0; i < 4; i++) {
                    int idx = tx + i * 256;
                    int row = idx >> 3, gg = idx & 7;
                    uint32_t so = (uint32_t)row * (RPAD * 2) + (uint32_t)gg * 16;
                    size_t  go = (size_t)row * 512 + kc + gg * 8;
                    CP16(shh[nb] + so, hcH + go);
                    CP16(shl[nb] + so, hcL + go);
                }
                CP_COMMIT();
                CP_WAIT1();
            } else {
                CP_WAIT0();
            }
            __syncthreads();
            const bf16* Sh = (const bf16*)(sm8 + (buf ? OFF_HH1 : OFF_HH0));
            const bf16* Sl = (const bf16*)(sm8 + (buf ? OFF_HL1 : OFF_HL0));
#pragma unroll
            for (int k16 = 0; k16 < 64; k16 += 16) {
                uint32_t ah[2][4], al[2][4];
#pragma unroll
                for (int tm = 0; tm < 2; tm++) {
                    const bf16* p = Sh + (m0w + tm * 16 + g) * RPAD + k16 + 2 * tig;
                    ah[tm][0] = *(const uint32_t*)(p);
                    ah[tm][1] = *(const uint32_t*)(p + 8 * RPAD);
                    ah[tm][2] = *(const uint32_t*)(p + 8);
                    ah[tm][3] = *(const uint32_t*)(p + 8 * RPAD + 8);
                    const bf16* q = Sl + (m0w + tm * 16 + g) * RPAD + k16 + 2 * tig;
                    al[tm][0] = *(const uint32_t*)(q);
                    al[tm][1] = *(const uint32_t*)(q + 8 * RPAD);
                    al[tm][2] = *(const uint32_t*)(q + 8);
                    al[tm][3] = *(const uint32_t*)(q + 8 * RPAD + 8);
                }
                const int kglob = c * 64 + k16 + 2 * tig;
                uint32_t bh[2][2], bl[2][2];
#pragma unroll
                for (int tn = 0; tn < 2; tn++) {
                    const bf16* p = sWh + (wc * 16 + tn * 8 + g) * WPAD + kglob;
                    bh[tn][0] = *(const uint32_t*)(p);
                    bh[tn][1] = *(const uint32_t*)(p + 8);
                    const bf16* q = sWl + (wc * 16 + tn * 8 + g) * WPAD + kglob;
                    bl[tn][0] = *(const uint32_t*)(q);
                    bl[tn][1] = *(const uint32_t*)(q + 8);
                }
#pragma unroll
                for (int tm = 0; tm < 2; tm++)
#pragma unroll
                    for (int tn = 0; tn < 2; tn++) {
                        MMA16816(acc[tm][tn], ah[tm], bh[tn]);
                        MMA16816(acc[tm][tn], ah[tm], bl[tn]);
                        MMA16816(acc[tm][tn], al[tm], bh[tn]);
                    }
            }
            __syncthreads();
        }

        // publish gate preactivations (h-part) to sg
#pragma unroll
        for (int tm = 0; tm < 2; tm++)
#pragma unroll
            for (int tn = 0; tn < 2; tn++) {
                int r = m0w + 16 * tm + g;
                int c0i = wc * 16 + tn * 8 + 2 * tig;
                *(float2*)&sg[r * SGPAD + c0i]       = make_float2(acc[tm][tn][0], acc[tm][tn][1]);
                *(float2*)&sg[(r + 8) * SGPAD + c0i] = make_float2(acc[tm][tn][2], acc[tm][tn][3]);
            }
        __syncthreads();

        // elementwise update (gate order i,f,g,o); b = tx>>1, 4 cols each
        {
            const int b  = tx >> 1;
            const int kb = (tx & 1) << 2;
            const float mcur = smk[b];
            const float mnxt = smk[128 + b];
            const size_t grow = (size_t)(b * TT + t) * G4 + hc0 + kb;
            float4 gi4 = *(const float4*)(Gx + grow);
            float4 gf4 = *(const float4*)(Gx + grow + 512);
            float4 gg4 = *(const float4*)(Gx + grow + 1024);
            float4 go4 = *(const float4*)(Gx + grow + 1536);
            float gi_[4] = {gi4.x, gi4.y, gi4.z, gi4.w};
            float gf_[4] = {gf4.x, gf4.y, gf4.z, gf4.w};
            float gg_[4] = {gg4.x, gg4.y, gg4.z, gg4.w};
            float go_[4] = {go4.x, go4.y, go4.z, go4.w};
            float hn[4];
#pragma unroll
            for (int i = 0; i < 4; i++) {
                int q = kb + i;
                float vi = sg[b * SGPAD + q]      + gi_[i];
                float vf = sg[b * SGPAD + 8 + q]  + gf_[i];
                float vg = sg[b * SGPAD + 16 + q] + gg_[i];
                float vo = sg[b * SGPAD + 24 + q] + go_[i];
                float cc = sc[b * 8 + q] * mcur;
                float cn = sigf(vf) * cc + sigf(vi) * tanhf(vg);
                hn[i] = sigf(vo) * tanhf(cn);
                sc[b * 8 + q] = cn;
            }
            // Y (unmasked) bf16 split
            {
                size_t yo = (size_t)(b * TT + t) * HH + hc0 + kb;
                __nv_bfloat162 h01, h23, l01, l23;
                h01.x = __float2bfloat16_rn(hn[0]); h01.y = __float2bfloat16_rn(hn[1]);
                h23.x = __float2bfloat16_rn(hn[2]); h23.y = __float2bfloat16_rn(hn[3]);
                l01.x = __float2bfloat16_rn(hn[0] - __bfloat162float(h01.x));
                l01.y = __float2bfloat16_rn(hn[1] - __bfloat162float(h01.y));
                l23.x = __float2bfloat16_rn(hn[2] - __bfloat162float(h23.x));
                l23.y = __float2bfloat16_rn(hn[3] - __bfloat162float(h23.y));
                *(__nv_bfloat162*)(Yh + yo)     = h01;
                *(__nv_bfloat162*)(Yh + yo + 2) = h23;
                *(__nv_bfloat162*)(Yl + yo)     = l01;
                *(__nv_bfloat162*)(Yl + yo + 2) = l23;
            }
            // next-step h (pre-masked with m_{t+1}) bf16 split
            if (t + 1 < TT) {
                bf16* hnH = hhb + ((t + 1) & 1) * BB * HH;
                bf16* hnL = hlb + ((t + 1) & 1) * BB * HH;
                size_t ho = (size_t)b * HH + hc0 + kb;
                __nv_bfloat162 h01, h23, l01, l23;
                float v0 = hn[0] * mnxt, v1 = hn[1] * mnxt, v2 = hn[2] * mnxt, v3 = hn[3] * mnxt;
                h01.x = __float2bfloat16_rn(v0); h01.y = __float2bfloat16_rn(v1);
                h23.x = __float2bfloat16_rn(v2); h23.y = __float2bfloat16_rn(v3);
                l01.x = __float2bfloat16_rn(v0 - __bfloat162float(h01.x));
                l01.y = __float2bfloat16_rn(v1 - __bfloat162float(h01.y));
                l23.x = __float2bfloat16_rn(v2 - __bfloat162float(h23.x));
                l23.y = __float2bfloat16_rn(v3 - __bfloat162float(h23.y));
                *(__nv_bfloat162*)(hnH + ho)     = h01;
                *(__nv_bfloat162*)(hnH + ho + 2) = h23;
                *(__nv_bfloat162*)(hnL + ho)     = l01;
                *(__nv_bfloat162*)(hnL + ho + 2) = l23;
            } else {
                // final h -> out (fp32, unmasked)
                float* oh = out + (size_t)3 * NR + (size_t)lstm * 2 * NR;
#pragma unroll
                for (int i = 0; i < 4; i++)
                    oh[b * HH + hc0 + kb + i] = hn[i];
            }
        }
        grid_bar(gridDim.x);
    }

    // final c -> out
    float* oc = out + (size_t)3 * NR + (size_t)lstm * 2 * NR + NR;
    for (int s = 0; s < 4; s++) {
        int idx = tx + s * 256;
        int b = idx >> 3, q = idx & 7;
        oc[b * HH + hc0 + q] = sc[b * 8 + q];
    }
}

// ---------------- heads ----------------
__global__ __launch_bounds__(128) void head_kernel(
    const float* __restrict__ Zpi, const float* __restrict__ Zvf,
    const float* __restrict__ aw, const float* __restrict__ ab,
    const float* __restrict__ cw, const float* __restrict__ cb,
    float* __restrict__ out)
{
    __shared__ float sx[512];
    __shared__ float slog[32];
    __shared__ float sval[4];
    const int n  = blockIdx.x;
    const int tx = threadIdx.x;

    ((float4*)sx)[tx] = ((const float4*)(Zpi + (size_t)n * 512))[tx];

    float4 xv = ((const float4*)(Zvf + (size_t)n * 512))[tx];
    float4 wv = ((const float4*)cw)[tx];
    float v = xv.x * wv.x + xv.y * wv.y + xv.z * wv.z + xv.w * wv.w;
#pragma unroll
    for (int off = 16; off; off >>= 1) v += __shfl_xor_sync(0xffffffffu, v, off);
    if ((tx & 31) == 0) sval[tx >> 5] = v;
    __syncthreads();

    const int l = tx >> 2;
    const int part = tx & 3;
    const float* wl = aw + l * 512 + part * 128;
    const float* xl = sx + part * 128;
    float s = 0.0f;
#pragma unroll 8
    for (int k4 = 0; k4 < 32; k4++) {
        float4 a = ((const float4*)xl)[k4];
        float4 w = ((const float4*)wl)[k4];
        s += a.x * w.x + a.y * w.y + a.z * w.z + a.w * w.w;
    }
    s += __shfl_xor_sync(0xffffffffu, s, 1);
    s += __shfl_xor_sync(0xffffffffu, s, 2);
    if (part == 0) slog[l] = s + ab[l];
    __syncthreads();

    if (tx < 32) {
        float lv = slog[tx];
        float m = lv; int mi = tx;
#pragma unroll
        for (int off = 16; off; off >>= 1) {
            float om = __shfl_xor_sync(0xffffffffu, m, off);
            int   oi = __shfl_xor_sync(0xffffffffu, mi, off);
            if (om > m || (om == m && oi < mi)) { m = om; mi = oi; }
        }
        float e = __expf(lv - m);
#pragma unroll
        for (int off = 16; off; off >>= 1) e += __shfl_xor_sync(0xffffffffu, e, off);
        if (tx == 0) {
            out[n] = (float)mi;
            out[(size_t)NR + n] = sval[0] + sval[1] + sval[2] + sval[3] + cb[0];
            out[(size_t)2 * NR + n] = -__logf(e);
        }
    }
}

// ---------------- launch ----------------
extern "C" void kernel_launch(void* const* d_in, const int* in_sizes, int n_in,
                              void* d_out, int out_size)
{
    const float* features = (const float*)d_in[0];
    const float* starts   = (const float*)d_in[1];
    const float* h0pi = (const float*)d_in[2];
    const float* c0pi = (const float*)d_in[3];
    const float* h0vf = (const float*)d_in[4];
    const float* c0vf = (const float*)d_in[5];
    const float* Wihpi = (const float*)d_in[6];
    const float* Whhpi = (const float*)d_in[7];
    const float* bihpi = (const float*)d_in[8];
    const float* bhhpi = (const float*)d_in[9];
    const float* Wihvf = (const float*)d_in[10];
    const float* Whhvf = (const float*)d_in[11];
    const float* bihvf = (const float*)d_in[12];
    const float* bhhvf = (const float*)d_in[13];
    const float* polw1 = (const float*)d_in[14];
    const float* polb1 = (const float*)d_in[15];
    const float* polw2 = (const float*)d_in[16];
    const float* polb2 = (const float*)d_in[17];
    const float* valw1 = (const float*)d_in[18];
    const float* valb1 = (const float*)d_in[19];
    const float* valw2 = (const float*)d_in[20];
    const float* valb2 = (const float*)d_in[21];
    const float* aw = (const float*)d_in[22];
    const float* ab = (const float*)d_in[23];
    const float* cw = (const float*)d_in[24];
    const float* cb = (const float*)d_in[25];

    float *Gpi, *Gvf, *Z2pi, *Z2vf;
    cudaGetSymbolAddress((void**)&Gpi,  g_Gpi);
    cudaGetSymbolAddress((void**)&Gvf,  g_Gvf);
    cudaGetSymbolAddress((void**)&Z2pi, g_Z2pi);
    cudaGetSymbolAddress((void**)&Z2vf, g_Z2vf);
    bf16 *fh, *fl, *yph, *ypl, *yvh, *yvl, *z1ph, *z1pl, *z1vh, *z1vl, *wh, *wlp, *hh, *hl;
    cudaGetSymbolAddress((void**)&fh,  g_feat_h);
    cudaGetSymbolAddress((void**)&fl,  g_feat_l);
    cudaGetSymbolAddress((void**)&yph, g_ypi_h);
    cudaGetSymbolAddress((void**)&ypl, g_ypi_l);
    cudaGetSymbolAddress((void**)&yvh, g_yvf_h);
    cudaGetSymbolAddress((void**)&yvl, g_yvf_l);
    cudaGetSymbolAddress((void**)&z1ph, g_z1p_h);
    cudaGetSymbolAddress((void**)&z1pl, g_z1p_l);
    cudaGetSymbolAddress((void**)&z1vh, g_z1v_h);
    cudaGetSymbolAddress((void**)&z1vl, g_z1v_l);
    cudaGetSymbolAddress((void**)&wh,  g_w_h);
    cudaGetSymbolAddress((void**)&wlp, g_w_l);
    cudaGetSymbolAddress((void**)&hh,  g_hh);
    cudaGetSymbolAddress((void**)&hl,  g_hl);
    float* out = (float*)d_out;

    size_t tg_smem = (size_t)2 * STGB * sizeof(bf16);
    cudaFuncSetAttribute((const void*)tgemm, cudaFuncAttributeMaxDynamicSharedMemorySize, (int)tg_smem);
    cudaFuncSetAttribute((const void*)lstm_recur, cudaFuncAttributeMaxDynamicSharedMemorySize, LSTM_SMEM);

    // converts: features + weights
    cvt_pair<<<2048, 256>>>(features, fh, fl, (size_t)NR * DD / 4);
    cvt_pair<<<256, 256>>>(Wihpi, wh + WOFF_IHPI, wlp + WOFF_IHPI, (size_t)G4 * DD / 4);
    cvt_pair<<<256, 256>>>(Wihvf, wh + WOFF_IHVF, wlp + WOFF_IHVF, (size_t)G4 * DD / 4);
    cvt_pair<<<128, 256>>>(polw1, wh + WOFF_PW1, wlp + WOFF_PW1, (size_t)HH * HH / 4);
    cvt_pair<<<128, 256>>>(polw2, wh + WOFF_PW2, wlp + WOFF_PW2, (size_t)HH * HH / 4);
    cvt_pair<<<128, 256>>>(valw1, wh + WOFF_VW1, wlp + WOFF_VW1, (size_t)HH * HH / 4);
    cvt_pair<<<128, 256>>>(valw2, wh + WOFF_VW2, wlp + WOFF_VW2, (size_t)HH * HH / 4);

    // input GEMMs: G = X @ Wih^T + bih + bhh (fp32 out)
    tgemm<<<dim3(G4 / 128, NR / 128), 256, tg_smem>>>(fh, fl, wh + WOFF_IHPI, wlp + WOFF_IHPI,
                                                      bihpi, bhhpi, Gpi, nullptr, nullptr, G4, 0);
    tgemm<<<dim3(G4 / 128, NR / 128), 256, tg_smem>>>(fh, fl, wh + WOFF_IHVF, wlp + WOFF_IHVF,
                                                      bihvf, bhhvf, Gvf, nullptr, nullptr, G4, 0);

    // recurrence (writes Y directly as bf16 hi/lo)
    lstm_recur<<<128, 256, LSTM_SMEM>>>(Gpi, Gvf, starts, h0pi, c0pi, h0vf, c0vf,
                                        Whhpi, Whhvf, yph, ypl, yvh, yvl, hh, hl, out);

    // MLP layer 1 (bf16-split out, relu)
    tgemm<<<dim3(HH / 128, NR / 128), 256, tg_smem>>>(yph, ypl, wh + WOFF_PW1, wlp + WOFF_PW1,
                                                      polb1, nullptr, nullptr, z1ph, z1pl, HH, 1);
    tgemm<<<dim3(HH / 128, NR / 128), 256, tg_smem>>>(yvh, yvl, wh + WOFF_VW1, wlp + WOFF_VW1,
                                                      valb1, nullptr, nullptr, z1vh, z1vl, HH, 1);

    // MLP layer 2 (fp32 out)
    tgemm<<<dim3(HH / 128, NR / 128), 256, tg_smem>>>(z1ph, z1pl, wh + WOFF_PW2, wlp + WOFF_PW2,
                                                      polb2, nullptr, Z2pi, nullptr, nullptr, HH, 0);
    tgemm<<<dim3(HH / 128, NR / 128), 256, tg_smem>>>(z1vh, z1vl, wh + WOFF_VW2, wlp + WOFF_VW2,
                                                      valb2, nullptr, Z2vf, nullptr, nullptr, HH, 0);

    // heads
    head_kernel<<<NR, 128>>>(Z2pi, Z2vf, aw, ab, cw, cb, out);
}

// round 7
// speedup vs baseline: 2.0367x; 1.1116x over previous
#include <cuda_runtime.h>
#include <cuda_bf16.h>
#include <math.h>
#include <stdint.h>

// Problem constants
#define BB 128
#define TT 512
#define DD 512
#define HH 512
#define G4 2048
#define NR (BB*TT)
#define AA 32

typedef __nv_bfloat16 bf16;

// ---------------- scratch (device globals) ----------------
__device__ float g_Gpi[(size_t)NR * G4];
__device__ float g_Gvf[(size_t)NR * G4];
__device__ float g_Z2pi[(size_t)NR * HH];
__device__ float g_Z2vf[(size_t)NR * HH];
__device__ unsigned g_bar_count4[4];
__device__ unsigned g_bar_gen4[4];

// bf16 hi/lo pairs
__device__ __align__(16) bf16 g_feat_h[(size_t)NR * DD];
__device__ __align__(16) bf16 g_feat_l[(size_t)NR * DD];
__device__ __align__(16) bf16 g_ypi_h[(size_t)NR * HH];
__device__ __align__(16) bf16 g_ypi_l[(size_t)NR * HH];
__device__ __align__(16) bf16 g_yvf_h[(size_t)NR * HH];
__device__ __align__(16) bf16 g_yvf_l[(size_t)NR * HH];
__device__ __align__(16) bf16 g_z1p_h[(size_t)NR * HH];
__device__ __align__(16) bf16 g_z1p_l[(size_t)NR * HH];
__device__ __align__(16) bf16 g_z1v_h[(size_t)NR * HH];
__device__ __align__(16) bf16 g_z1v_l[(size_t)NR * HH];
// h ping-pong: [lstm][pingpong][128][512], bf16 hi/lo (pre-masked for the consuming step)
__device__ __align__(16) bf16 g_hh[2 * 2 * BB * HH];
__device__ __align__(16) bf16 g_hl[2 * 2 * BB * HH];
// weights blob
#define WOFF_IHPI 0
#define WOFF_IHVF 1048576
#define WOFF_PW1  2097152
#define WOFF_PW2  2359296
#define WOFF_VW1  2621440
#define WOFF_VW2  2883584
#define WTOT      3145728
__device__ __align__(16) bf16 g_w_h[WTOT];
__device__ __align__(16) bf16 g_w_l[WTOT];

__device__ __forceinline__ float sigf(float x) { return 1.0f / (1.0f + __expf(-x)); }

// ---------------- PTX helpers ----------------
#define CP16(d, s) asm volatile("cp.async.cg.shared.global [%0], [%1], 16;" :: "r"(d), "l"(s) : "memory")
#define CP_COMMIT() asm volatile("cp.async.commit_group;" ::: "memory")
#define CP_WAIT0()  asm volatile("cp.async.wait_group 0;" ::: "memory")
#define CP_WAIT1()  asm volatile("cp.async.wait_group 1;" ::: "memory")

__device__ __forceinline__ uint32_t smem_u32(const void* p) {
    uint32_t a;
    asm("{ .reg .u64 t; cvta.to.shared.u64 t, %1; cvt.u32.u64 %0, t; }" : "=r"(a) : "l"(p));
    return a;
}

#define MMA16816(c, a, b) \
    asm volatile("mma.sync.aligned.m16n8k16.row.col.f32.bf16.bf16.f32 " \
        "{%0,%1,%2,%3}, {%4,%5,%6,%7}, {%8,%9}, {%0,%1,%2,%3};" \
        : "+f"((c)[0]), "+f"((c)[1]), "+f"((c)[2]), "+f"((c)[3]) \
        : "r"((a)[0]), "r"((a)[1]), "r"((a)[2]), "r"((a)[3]), "r"((b)[0]), "r"((b)[1]))

// ---------------- fp32 -> bf16 hi/lo converter ----------------
__global__ __launch_bounds__(256) void cvt_pair(const float* __restrict__ x,
                                                bf16* __restrict__ hi, bf16* __restrict__ lo, size_t n4)
{
    for (size_t i = blockIdx.x * blockDim.x + threadIdx.x; i < n4; i += (size_t)gridDim.x * blockDim.x) {
        float4 v = ((const float4*)x)[i];
        bf16 h0 = __float2bfloat16_rn(v.x), h1 = __float2bfloat16_rn(v.y);
        bf16 h2 = __float2bfloat16_rn(v.z), h3 = __float2bfloat16_rn(v.w);
        bf16 l0 = __float2bfloat16_rn(v.x - __bfloat162float(h0));
        bf16 l1 = __float2bfloat16_rn(v.y - __bfloat162float(h1));
        bf16 l2 = __float2bfloat16_rn(v.z - __bfloat162float(h2));
        bf16 l3 = __float2bfloat16_rn(v.w - __bfloat162float(h3));
        __nv_bfloat162 hp0; hp0.x = h0; hp0.y = h1;
        __nv_bfloat162 hp1; hp1.x = h2; hp1.y = h3;
        __nv_bfloat162 lp0; lp0.x = l0; lp0.y = l1;
        __nv_bfloat162 lp1; lp1.x = l2; lp1.y = l3;
        ((__nv_bfloat162*)hi)[2 * i]     = hp0;
        ((__nv_bfloat162*)hi)[2 * i + 1] = hp1;
        ((__nv_bfloat162*)lo)[2 * i]     = lp0;
        ((__nv_bfloat162*)lo)[2 * i + 1] = lp1;
    }
}

// ---------------- HMMA bf16-split GEMM (unchanged from R5) ----------------
#define KSTG 32
#define ROWP 40
#define MATB (128 * ROWP)
#define STGB (4 * MATB)
__global__ __launch_bounds__(256, 1) void tgemm(
    const bf16* __restrict__ Ah, const bf16* __restrict__ Al,
    const bf16* __restrict__ Wh, const bf16* __restrict__ Wl,
    const float* __restrict__ b1, const float* __restrict__ b2,
    float* __restrict__ C, bf16* __restrict__ Ch, bf16* __restrict__ Cl,
    int N, int relu)
{
    extern __shared__ bf16 smbf[];
    const int tid  = threadIdx.x;
    const int wid  = tid >> 5, lane = tid & 31;
    const int g    = lane >> 2, tig = lane & 3;
    const int m0   = (wid & 3) * 32;
    const int n0   = (wid >> 2) * 64;
    const size_t arow0 = (size_t)blockIdx.y * 128;
    const size_t brow0 = (size_t)blockIdx.x * 128;

    const int lmat = tid >> 6, t64 = tid & 63;
    const bf16* gsrc;
    if      (lmat == 0) gsrc = Ah + arow0 * 512;
    else if (lmat == 1) gsrc = Al + arow0 * 512;
    else if (lmat == 2) gsrc = Wh + brow0 * 512;
    else                gsrc = Wl + brow0 * 512;
    const uint32_t sbase = smem_u32(smbf);
    const uint32_t sdstm = sbase + (uint32_t)lmat * (MATB * 2);

    float acc[2][8][4];
#pragma unroll
    for (int i = 0; i < 2; i++)
#pragma unroll
        for (int j = 0; j < 8; j++)
#pragma unroll
            for (int q = 0; q < 4; q++) acc[i][j][q] = 0.0f;

#pragma unroll
    for (int s = 0; s < 2; s++) {
        const uint32_t db = sdstm + (uint32_t)s * (STGB * 2);
        const int k0 = s * KSTG;
#pragma unroll
        for (int i = 0; i < 8; i++) {
            int idx = i * 64 + t64;
            int row = idx >> 2, gg = idx & 3;
            CP16(db + (uint32_t)row * (ROWP * 2) + (uint32_t)gg * 16,
                 gsrc + (size_t)row * 512 + k0 + gg * 8);
        }
        CP_COMMIT();
    }

    const int NSTG = 512 / KSTG;
#pragma unroll 1
    for (int c = 0; c < NSTG; c++) {
        if (c < NSTG - 2) { CP_WAIT1(); } else { CP_WAIT0(); }
        __syncthreads();
        const bf16* S   = smbf + (size_t)(c & 1) * STGB;
        const bf16* sAh = S;
        const bf16* sAl = S + MATB;
        const bf16* sWh = S + 2 * MATB;
        const bf16* sWl = S + 3 * MATB;
#pragma unroll
        for (int kk = 0; kk < KSTG; kk += 16) {
            uint32_t ah[2][4], al[2][4];
#pragma unroll
            for (int tm = 0; tm < 2; tm++) {
                const bf16* p = sAh + (m0 + tm * 16 + g) * ROWP + kk + 2 * tig;
                ah[tm][0] = *(const uint32_t*)(p);
                ah[tm][1] = *(const uint32_t*)(p + 8 * ROWP);
                ah[tm][2] = *(const uint32_t*)(p + 8);
                ah[tm][3] = *(const uint32_t*)(p + 8 * ROWP + 8);
                const bf16* q = sAl + (m0 + tm * 16 + g) * ROWP + kk + 2 * tig;
                al[tm][0] = *(const uint32_t*)(q);
                al[tm][1] = *(const uint32_t*)(q + 8 * ROWP);
                al[tm][2] = *(const uint32_t*)(q + 8);
                al[tm][3] = *(const uint32_t*)(q + 8 * ROWP + 8);
            }
            uint32_t bh[8][2], bl[8][2];
#pragma unroll
            for (int tn = 0; tn < 8; tn++) {
                const bf16* p = sWh + (n0 + tn * 8 + g) * ROWP + kk + 2 * tig;
                bh[tn][0] = *(const uint32_t*)(p);
                bh[tn][1] = *(const uint32_t*)(p + 8);
                const bf16* q = sWl + (n0 + tn * 8 + g) * ROWP + kk + 2 * tig;
                bl[tn][0] = *(const uint32_t*)(q);
                bl[tn][1] = *(const uint32_t*)(q + 8);
            }
#pragma unroll
            for (int tm = 0; tm < 2; tm++)
#pragma unroll
                for (int tn = 0; tn < 8; tn++) {
                    MMA16816(acc[tm][tn], ah[tm], bh[tn]);
                    MMA16816(acc[tm][tn], ah[tm], bl[tn]);
                    MMA16816(acc[tm][tn], al[tm], bh[tn]);
                }
        }
        __syncthreads();
        if (c + 2 < NSTG) {
            const uint32_t db = sdstm + (uint32_t)(c & 1) * (STGB * 2);
            const int k0 = (c + 2) * KSTG;
#pragma unroll
            for (int i = 0; i < 8; i++) {
                int idx = i * 64 + t64;
                int row = idx >> 2, gg = idx & 3;
                CP16(db + (uint32_t)row * (ROWP * 2) + (uint32_t)gg * 16,
                     gsrc + (size_t)row * 512 + k0 + gg * 8);
            }
            CP_COMMIT();
        }
    }

#pragma unroll
    for (int tn = 0; tn < 8; tn++) {
        int cc = (int)brow0 + n0 + tn * 8 + 2 * tig;
        float bv0 = b1[cc]     + (b2 ? b2[cc]     : 0.0f);
        float bv1 = b1[cc + 1] + (b2 ? b2[cc + 1] : 0.0f);
#pragma unroll
        for (int tm = 0; tm < 2; tm++) {
            size_t r0 = arow0 + m0 + tm * 16 + g;
            float v[4];
            v[0] = acc[tm][tn][0] + bv0;
            v[1] = acc[tm][tn][1] + bv1;
            v[2] = acc[tm][tn][2] + bv0;
            v[3] = acc[tm][tn][3] + bv1;
            if (relu) {
#pragma unroll
                for (int q = 0; q < 4; q++) v[q] = fmaxf(v[q], 0.f);
            }
            if (Ch) {
                __nv_bfloat162 h0, h1, l0, l1;
                h0.x = __float2bfloat16_rn(v[0]); h0.y = __float2bfloat16_rn(v[1]);
                h1.x = __float2bfloat16_rn(v[2]); h1.y = __float2bfloat16_rn(v[3]);
                l0.x = __float2bfloat16_rn(v[0] - __bfloat162float(h0.x));
                l0.y = __float2bfloat16_rn(v[1] - __bfloat162float(h0.y));
                l1.x = __float2bfloat16_rn(v[2] - __bfloat162float(h1.x));
                l1.y = __float2bfloat16_rn(v[3] - __bfloat162float(h1.y));
                *(__nv_bfloat162*)(Ch + r0 * (size_t)N + cc)       = h0;
                *(__nv_bfloat162*)(Cl + r0 * (size_t)N + cc)       = l0;
                *(__nv_bfloat162*)(Ch + (r0 + 8) * (size_t)N + cc) = h1;
                *(__nv_bfloat162*)(Cl + (r0 + 8) * (size_t)N + cc) = l1;
            } else {
                *(float2*)(C + r0 * (size_t)N + cc)       = make_float2(v[0], v[1]);
                *(float2*)(C + (r0 + 8) * (size_t)N + cc) = make_float2(v[2], v[3]);
            }
        }
    }
}

// ---------------- per-group software barrier (32 CTAs per group) ----------------
__device__ __forceinline__ void grid_bar_grp(int grp, int nct) {
    __threadfence();
    __syncthreads();
    if (threadIdx.x == 0) {
        volatile unsigned* vgen = &g_bar_gen4[grp];
        unsigned g = *vgen;
        unsigned a = atomicAdd(&g_bar_count4[grp], 1u);
        if (a == (unsigned)nct - 1u) {
            g_bar_count4[grp] = 0u;
            __threadfence();
            atomicAdd(&g_bar_gen4[grp], 1u);
        } else {
            while (*vgen == g) { }
        }
        __threadfence();
    }
    __syncthreads();
}

// ---------------- persistent recurrent kernel: HMMA bf16-split, batch-split ----------------
// 128 CTAs x 256 thr. ct: lstm = ct>>6, bh = (ct>>5)&1 (batch half, 64 rows), cid = ct&31
// (16 h-cols -> 64 gate-cols). Barrier group = ct>>5 (32 CTAs, fully independent).
// Per step: gates[64,64] = h[64,512] @ WhhT_slice[512,64], m16n8k16, 3-pass split.
#define RPAD 72
#define WPAD 520
#define SGPAD 72
#define OFF_WH   0
#define OFF_WL   (64 * WPAD * 2)
#define OFF_HH0  (2 * 64 * WPAD * 2)
#define OFF_HH1  (OFF_HH0 + 64 * RPAD * 2)
#define OFF_HL0  (OFF_HH0 + 2 * 64 * RPAD * 2)
#define OFF_HL1  (OFF_HL0 + 64 * RPAD * 2)
#define OFF_SG   (OFF_HH0 + 4 * 64 * RPAD * 2)
#define OFF_MASK (OFF_SG + 64 * SGPAD * 4)
#define OFF_SC   (OFF_MASK + 128 * 4)
#define LSTM_SMEM (OFF_SC + 64 * 16 * 4)

__global__ __launch_bounds__(256, 1) void lstm_recur(
    const float* __restrict__ Gpi, const float* __restrict__ Gvf,
    const float* __restrict__ starts,
    const float* __restrict__ h0pi, const float* __restrict__ c0pi,
    const float* __restrict__ h0vf, const float* __restrict__ c0vf,
    const float* __restrict__ Whhpi, const float* __restrict__ Whhvf,
    bf16* __restrict__ Yph, bf16* __restrict__ Ypl,
    bf16* __restrict__ Yvh, bf16* __restrict__ Yvl,
    bf16* __restrict__ hhg, bf16* __restrict__ hlg,
    float* __restrict__ out)
{
    extern __shared__ char sm8[];
    bf16*  sWh = (bf16*)(sm8 + OFF_WH);
    bf16*  sWl = (bf16*)(sm8 + OFF_WL);
    float* sg  = (float*)(sm8 + OFF_SG);
    float* smk = (float*)(sm8 + OFF_MASK);
    float* sc  = (float*)(sm8 + OFF_SC);

    const int ct   = blockIdx.x;
    const int lstm = ct >> 6;
    const int grp  = ct >> 5;            // 0..3
    const int b0   = ((ct >> 5) & 1) * 64;
    const int cid  = ct & 31;
    const int hc0  = cid * 16;
    const int tx   = threadIdx.x;
    const int wid  = tx >> 5, lane = tx & 31;
    const int g    = lane >> 2, tig = lane & 3;
    const int m0w  = (wid & 1) * 32;     // batch-row block (within 64)
    const int n0w  = (wid >> 1) * 16;    // gate-col block (within 64)

    const float* Gx  = lstm ? Gvf   : Gpi;
    const float* Whh = lstm ? Whhvf : Whhpi;
    const float* h0  = lstm ? h0vf  : h0pi;
    const float* c0  = lstm ? c0vf  : c0pi;
    bf16* Yh = lstm ? Yvh : Yph;
    bf16* Yl = lstm ? Yvl : Ypl;
    bf16* hhb = hhg + lstm * 2 * BB * HH;
    bf16* hlb = hlg + lstm * 2 * BB * HH;

    const uint32_t sb = smem_u32(sm8);
    const uint32_t shh[2] = { sb + OFF_HH0, sb + OFF_HH1 };
    const uint32_t shl[2] = { sb + OFF_HL0, sb + OFF_HL1 };

    // load + split Whh slice: 64 gate-cols j = gate*16 + q -> global row (j>>4)*512 + hc0 + (j&15)
    for (int s = 0; s < 128; s++) {
        int idx = tx + s * 256;          // 0..32767
        int j = idx >> 9, k = idx & 511;
        int gc = ((j >> 4) << 9) + hc0 + (j & 15);
        float w = Whh[(size_t)gc * HH + k];
        bf16 hi = __float2bfloat16_rn(w);
        sWh[j * WPAD + k] = hi;
        sWl[j * WPAD + k] = __float2bfloat16_rn(w - __bfloat162float(hi));
    }
    // init c (smem) and h0 (ping 0, pre-masked with m0, bf16 split): rows b0..b0+63, cols hc0..+15
    for (int s = 0; s < 4; s++) {
        int idx = tx + s * 256;          // 0..1023
        int br = idx >> 4, q = idx & 15;
        int b = b0 + br;
        sc[br * 16 + q] = c0[b * HH + hc0 + q];
        float m0 = 1.0f - starts[b * TT];
        float v = h0[b * HH + hc0 + q] * m0;
        bf16 hi = __float2bfloat16_rn(v);
        hhb[b * HH + hc0 + q] = hi;
        hlb[b * HH + hc0 + q] = __float2bfloat16_rn(v - __bfloat162float(hi));
    }
    grid_bar_grp(grp, 32);

    // elementwise geometry (fixed per thread)
    const int ebr = tx >> 2;             // 0..63 local batch row
    const int ekb = (tx & 3) << 2;       // 0,4,8,12 (h-col offset)
    const int eb  = b0 + ebr;            // global batch row

    for (int t = 0; t < TT; t++) {
        const int cur = t & 1;
        const bf16* hcH = hhb + cur * BB * HH;
        const bf16* hcL = hlb + cur * BB * HH;

        // G prefetch for this step (hidden behind MMA loop)
        const size_t grow = ((size_t)eb * TT + t) * G4 + hc0 + ekb;
        const float4 pgi = *(const float4*)(Gx + grow);
        const float4 pgf = *(const float4*)(Gx + grow + 512);
        const float4 pgg = *(const float4*)(Gx + grow + 1024);
        const float4 pgo = *(const float4*)(Gx + grow + 1536);

        // prefetch h chunk 0 (K 0..63): 1024 granules of 16B (hi 512 + lo 512)
#pragma unroll
        for (int i = 0; i < 4; i++) {
            int idx = tx + i * 256;
            int m = idx >> 9;
            int g512 = idx & 511;
            int row = g512 >> 3, gg = g512 & 7;
            uint32_t so = (uint32_t)row * (RPAD * 2) + (uint32_t)gg * 16;
            size_t  go = (size_t)(b0 + row) * 512 + gg * 8;
            if (m) CP16(shl[0] + so, hcL + go);
            else   CP16(shh[0] + so, hcH + go);
        }
        CP_COMMIT();

        // masks for rows b0..b0+63 (cur and next)
        if (tx < 64) smk[tx] = 1.0f - starts[(b0 + tx) * TT + t];
        else if (tx < 128) {
            int br = tx - 64;
            smk[64 + br] = (t + 1 < TT) ? (1.0f - starts[(b0 + br) * TT + t + 1]) : 1.0f;
        }

        float acc[2][2][4];
#pragma unroll
        for (int tm = 0; tm < 2; tm++)
#pragma unroll
            for (int tn = 0; tn < 2; tn++)
#pragma unroll
                for (int q = 0; q < 4; q++) acc[tm][tn][q] = 0.0f;

#pragma unroll 1
        for (int c = 0; c < 8; c++) {
            const int buf = c & 1;
            if (c < 7) {
                const int nb = buf ^ 1;
                const int kc = (c + 1) * 64;
#pragma unroll
                for (int i = 0; i < 4; i++) {
                    int idx = tx + i * 256;
                    int m = idx >> 9;
                    int g512 = idx & 511;
                    int row = g512 >> 3, gg = g512 & 7;
                    uint32_t so = (uint32_t)row * (RPAD * 2) + (uint32_t)gg * 16;
                    size_t  go = (size_t)(b0 + row) * 512 + kc + gg * 8;
                    if (m) CP16(shl[nb] + so, hcL + go);
                    else   CP16(shh[nb] + so, hcH + go);
                }
                CP_COMMIT();
                CP_WAIT1();
            } else {
                CP_WAIT0();
            }
            __syncthreads();
            const bf16* Sh = (const bf16*)(sm8 + (buf ? OFF_HH1 : OFF_HH0));
            const bf16* Sl = (const bf16*)(sm8 + (buf ? OFF_HL1 : OFF_HL0));
#pragma unroll
            for (int k16 = 0; k16 < 64; k16 += 16) {
                uint32_t ah[2][4], al[2][4];
#pragma unroll
                for (int tm = 0; tm < 2; tm++) {
                    const bf16* p = Sh + (m0w + tm * 16 + g) * RPAD + k16 + 2 * tig;
                    ah[tm][0] = *(const uint32_t*)(p);
                    ah[tm][1] = *(const uint32_t*)(p + 8 * RPAD);
                    ah[tm][2] = *(const uint32_t*)(p + 8);
                    ah[tm][3] = *(const uint32_t*)(p + 8 * RPAD + 8);
                    const bf16* q = Sl + (m0w + tm * 16 + g) * RPAD + k16 + 2 * tig;
                    al[tm][0] = *(const uint32_t*)(q);
                    al[tm][1] = *(const uint32_t*)(q + 8 * RPAD);
                    al[tm][2] = *(const uint32_t*)(q + 8);
                    al[tm][3] = *(const uint32_t*)(q + 8 * RPAD + 8);
                }
                const int kglob = c * 64 + k16 + 2 * tig;
                uint32_t bh[2][2], bl[2][2];
#pragma unroll
                for (int tn = 0; tn < 2; tn++) {
                    const bf16* p = sWh + (n0w + tn * 8 + g) * WPAD + kglob;
                    bh[tn][0] = *(const uint32_t*)(p);
                    bh[tn][1] = *(const uint32_t*)(p + 8);
                    const bf16* q = sWl + (n0w + tn * 8 + g) * WPAD + kglob;
                    bl[tn][0] = *(const uint32_t*)(q);
                    bl[tn][1] = *(const uint32_t*)(q + 8);
                }
#pragma unroll
                for (int tm = 0; tm < 2; tm++)
#pragma unroll
                    for (int tn = 0; tn < 2; tn++) {
                        MMA16816(acc[tm][tn], ah[tm], bh[tn]);
                        MMA16816(acc[tm][tn], ah[tm], bl[tn]);
                        MMA16816(acc[tm][tn], al[tm], bh[tn]);
                    }
            }
            __syncthreads();
        }

        // publish gate preactivations (h-part) to sg [64 rows][64 cols packed gate*16+q]
#pragma unroll
        for (int tm = 0; tm < 2; tm++)
#pragma unroll
            for (int tn = 0; tn < 2; tn++) {
                int r = m0w + 16 * tm + g;
                int c0i = n0w + tn * 8 + 2 * tig;
                *(float2*)&sg[r * SGPAD + c0i]       = make_float2(acc[tm][tn][0], acc[tm][tn][1]);
                *(float2*)&sg[(r + 8) * SGPAD + c0i] = make_float2(acc[tm][tn][2], acc[tm][tn][3]);
            }
        __syncthreads();

        // elementwise update: thread -> (ebr, 4 h-cols at ekb)
        {
            const float mcur = smk[ebr];
            const float mnxt = smk[64 + ebr];
            const float gi_[4] = {pgi.x, pgi.y, pgi.z, pgi.w};
            const float gf_[4] = {pgf.x, pgf.y, pgf.z, pgf.w};
            const float gg_[4] = {pgg.x, pgg.y, pgg.z, pgg.w};
            const float go_[4] = {pgo.x, pgo.y, pgo.z, pgo.w};
            float hn[4];
#pragma unroll
            for (int i = 0; i < 4; i++) {
                int q = ekb + i;
                float vi = sg[ebr * SGPAD + q]      + gi_[i];
                float vf = sg[ebr * SGPAD + 16 + q] + gf_[i];
                float vg = sg[ebr * SGPAD + 32 + q] + gg_[i];
                float vo = sg[ebr * SGPAD + 48 + q] + go_[i];
                float cc = sc[ebr * 16 + q] * mcur;
                float cn = sigf(vf) * cc + sigf(vi) * tanhf(vg);
                hn[i] = sigf(vo) * tanhf(cn);
                sc[ebr * 16 + q] = cn;
            }
            // Y (unmasked) bf16 split
            {
                size_t yo = ((size_t)eb * TT + t) * HH + hc0 + ekb;
                __nv_bfloat162 h01, h23, l01, l23;
                h01.x = __float2bfloat16_rn(hn[0]); h01.y = __float2bfloat16_rn(hn[1]);
                h23.x = __float2bfloat16_rn(hn[2]); h23.y = __float2bfloat16_rn(hn[3]);
                l01.x = __float2bfloat16_rn(hn[0] - __bfloat162float(h01.x));
                l01.y = __float2bfloat16_rn(hn[1] - __bfloat162float(h01.y));
                l23.x = __float2bfloat16_rn(hn[2] - __bfloat162float(h23.x));
                l23.y = __float2bfloat16_rn(hn[3] - __bfloat162float(h23.y));
                *(__nv_bfloat162*)(Yh + yo)     = h01;
                *(__nv_bfloat162*)(Yh + yo + 2) = h23;
                *(__nv_bfloat162*)(Yl + yo)     = l01;
                *(__nv_bfloat162*)(Yl + yo + 2) = l23;
            }
            if (t + 1 < TT) {
                bf16* hnH = hhb + ((t + 1) & 1) * BB * HH;
                bf16* hnL = hlb + ((t + 1) & 1) * BB * HH;
                size_t ho = (size_t)eb * HH + hc0 + ekb;
                __nv_bfloat162 h01, h23, l01, l23;
                float v0 = hn[0] * mnxt, v1 = hn[1] * mnxt, v2 = hn[2] * mnxt, v3 = hn[3] * mnxt;
                h01.x = __float2bfloat16_rn(v0); h01.y = __float2bfloat16_rn(v1);
                h23.x = __float2bfloat16_rn(v2); h23.y = __float2bfloat16_rn(v3);
                l01.x = __float2bfloat16_rn(v0 - __bfloat162float(h01.x));
                l01.y = __float2bfloat16_rn(v1 - __bfloat162float(h01.y));
                l23.x = __float2bfloat16_rn(v2 - __bfloat162float(h23.x));
                l23.y = __float2bfloat16_rn(v3 - __bfloat162float(h23.y));
                *(__nv_bfloat162*)(hnH + ho)     = h01;
                *(__nv_bfloat162*)(hnH + ho + 2) = h23;
                *(__nv_bfloat162*)(hnL + ho)     = l01;
                *(__nv_bfloat162*)(hnL + ho + 2) = l23;
            } else {
                float* oh = out + (size_t)3 * NR + (size_t)lstm * 2 * NR;
#pragma unroll
                for (int i = 0; i < 4; i++)
                    oh[eb * HH + hc0 + ekb + i] = hn[i];
            }
        }
        grid_bar_grp(grp, 32);
    }

    // final c -> out
    float* oc = out + (size_t)3 * NR + (size_t)lstm * 2 * NR + NR;
    for (int s = 0; s < 4; s++) {
        int idx = tx + s * 256;
        int br = idx >> 4, q = idx & 15;
        oc[(b0 + br) * HH + hc0 + q] = sc[br * 16 + q];
    }
}

// ---------------- heads ----------------
__global__ __launch_bounds__(128) void head_kernel(
    const float* __restrict__ Zpi, const float* __restrict__ Zvf,
    const float* __restrict__ aw, const float* __restrict__ ab,
    const float* __restrict__ cw, const float* __restrict__ cb,
    float* __restrict__ out)
{
    __shared__ float sx[512];
    __shared__ float slog[32];
    __shared__ float sval[4];
    const int n  = blockIdx.x;
    const int tx = threadIdx.x;

    ((float4*)sx)[tx] = ((const float4*)(Zpi + (size_t)n * 512))[tx];

    float4 xv = ((const float4*)(Zvf + (size_t)n * 512))[tx];
    float4 wv = ((const float4*)cw)[tx];
    float v = xv.x * wv.x + xv.y * wv.y + xv.z * wv.z + xv.w * wv.w;
#pragma unroll
    for (int off = 16; off; off >>= 1) v += __shfl_xor_sync(0xffffffffu, v, off);
    if ((tx & 31) == 0) sval[tx >> 5] = v;
    __syncthreads();

    const int l = tx >> 2;
    const int part = tx & 3;
    const float* wl = aw + l * 512 + part * 128;
    const float* xl = sx + part * 128;
    float s = 0.0f;
#pragma unroll 8
    for (int k4 = 0; k4 < 32; k4++) {
        float4 a = ((const float4*)xl)[k4];
        float4 w = ((const float4*)wl)[k4];
        s += a.x * w.x + a.y * w.y + a.z * w.z + a.w * w.w;
    }
    s += __shfl_xor_sync(0xffffffffu, s, 1);
    s += __shfl_xor_sync(0xffffffffu, s, 2);
    if (part == 0) slog[l] = s + ab[l];
    __syncthreads();

    if (tx < 32) {
        float lv = slog[tx];
        float m = lv; int mi = tx;
#pragma unroll
        for (int off = 16; off; off >>= 1) {
            float om = __shfl_xor_sync(0xffffffffu, m, off);
            int   oi = __shfl_xor_sync(0xffffffffu, mi, off);
            if (om > m || (om == m && oi < mi)) { m = om; mi = oi; }
        }
        float e = __expf(lv - m);
#pragma unroll
        for (int off = 16; off; off >>= 1) e += __shfl_xor_sync(0xffffffffu, e, off);
        if (tx == 0) {
            out[n] = (float)mi;
            out[(size_t)NR + n] = sval[0] + sval[1] + sval[2] + sval[3] + cb[0];
            out[(size_t)2 * NR + n] = -__logf(e);
        }
    }
}

// ---------------- launch ----------------
extern "C" void kernel_launch(void* const* d_in, const int* in_sizes, int n_in,
                              void* d_out, int out_size)
{
    const float* features = (const float*)d_in[0];
    const float* starts   = (const float*)d_in[1];
    const float* h0pi = (const float*)d_in[2];
    const float* c0pi = (const float*)d_in[3];
    const float* h0vf = (const float*)d_in[4];
    const float* c0vf = (const float*)d_in[5];
    const float* Wihpi = (const float*)d_in[6];
    const float* Whhpi = (const float*)d_in[7];
    const float* bihpi = (const float*)d_in[8];
    const float* bhhpi = (const float*)d_in[9];
    const float* Wihvf = (const float*)d_in[10];
    const float* Whhvf = (const float*)d_in[11];
    const float* bihvf = (const float*)d_in[12];
    const float* bhhvf = (const float*)d_in[13];
    const float* polw1 = (const float*)d_in[14];
    const float* polb1 = (const float*)d_in[15];
    const float* polw2 = (const float*)d_in[16];
    const float* polb2 = (const float*)d_in[17];
    const float* valw1 = (const float*)d_in[18];
    const float* valb1 = (const float*)d_in[19];
    const float* valw2 = (const float*)d_in[20];
    const float* valb2 = (const float*)d_in[21];
    const float* aw = (const float*)d_in[22];
    const float* ab = (const float*)d_in[23];
    const float* cw = (const float*)d_in[24];
    const float* cb = (const float*)d_in[25];

    float *Gpi, *Gvf, *Z2pi, *Z2vf;
    cudaGetSymbolAddress((void**)&Gpi,  g_Gpi);
    cudaGetSymbolAddress((void**)&Gvf,  g_Gvf);
    cudaGetSymbolAddress((void**)&Z2pi, g_Z2pi);
    cudaGetSymbolAddress((void**)&Z2vf, g_Z2vf);
    bf16 *fh, *fl, *yph, *ypl, *yvh, *yvl, *z1ph, *z1pl, *z1vh, *z1vl, *wh, *wlp, *hh, *hl;
    cudaGetSymbolAddress((void**)&fh,  g_feat_h);
    cudaGetSymbolAddress((void**)&fl,  g_feat_l);
    cudaGetSymbolAddress((void**)&yph, g_ypi_h);
    cudaGetSymbolAddress((void**)&ypl, g_ypi_l);
    cudaGetSymbolAddress((void**)&yvh, g_yvf_h);
    cudaGetSymbolAddress((void**)&yvl, g_yvf_l);
    cudaGetSymbolAddress((void**)&z1ph, g_z1p_h);
    cudaGetSymbolAddress((void**)&z1pl, g_z1p_l);
    cudaGetSymbolAddress((void**)&z1vh, g_z1v_h);
    cudaGetSymbolAddress((void**)&z1vl, g_z1v_l);
    cudaGetSymbolAddress((void**)&wh,  g_w_h);
    cudaGetSymbolAddress((void**)&wlp, g_w_l);
    cudaGetSymbolAddress((void**)&hh,  g_hh);
    cudaGetSymbolAddress((void**)&hl,  g_hl);
    float* out = (float*)d_out;

    size_t tg_smem = (size_t)2 * STGB * sizeof(bf16);
    cudaFuncSetAttribute((const void*)tgemm, cudaFuncAttributeMaxDynamicSharedMemorySize, (int)tg_smem);
    cudaFuncSetAttribute((const void*)lstm_recur, cudaFuncAttributeMaxDynamicSharedMemorySize, LSTM_SMEM);

    // converts: features + weights
    cvt_pair<<<2048, 256>>>(features, fh, fl, (size_t)NR * DD / 4);
    cvt_pair<<<256, 256>>>(Wihpi, wh + WOFF_IHPI, wlp + WOFF_IHPI, (size_t)G4 * DD / 4);
    cvt_pair<<<256, 256>>>(Wihvf, wh + WOFF_IHVF, wlp + WOFF_IHVF, (size_t)G4 * DD / 4);
    cvt_pair<<<128, 256>>>(polw1, wh + WOFF_PW1, wlp + WOFF_PW1, (size_t)HH * HH / 4);
    cvt_pair<<<128, 256>>>(polw2, wh + WOFF_PW2, wlp + WOFF_PW2, (size_t)HH * HH / 4);
    cvt_pair<<<128, 256>>>(valw1, wh + WOFF_VW1, wlp + WOFF_VW1, (size_t)HH * HH / 4);
    cvt_pair<<<128, 256>>>(valw2, wh + WOFF_VW2, wlp + WOFF_VW2, (size_t)HH * HH / 4);

    // input GEMMs: G = X @ Wih^T + bih + bhh (fp32 out)
    tgemm<<<dim3(G4 / 128, NR / 128), 256, tg_smem>>>(fh, fl, wh + WOFF_IHPI, wlp + WOFF_IHPI,
                                                      bihpi, bhhpi, Gpi, nullptr, nullptr, G4, 0);
    tgemm<<<dim3(G4 / 128, NR / 128), 256, tg_smem>>>(fh, fl, wh + WOFF_IHVF, wlp + WOFF_IHVF,
                                                      bihvf, bhhvf, Gvf, nullptr, nullptr, G4, 0);

    // recurrence (writes Y directly as bf16 hi/lo)
    lstm_recur<<<128, 256, LSTM_SMEM>>>(Gpi, Gvf, starts, h0pi, c0pi, h0vf, c0vf,
                                        Whhpi, Whhvf, yph, ypl, yvh, yvl, hh, hl, out);

    // MLP layer 1 (bf16-split out, relu)
    tgemm<<<dim3(HH / 128, NR / 128), 256, tg_smem>>>(yph, ypl, wh + WOFF_PW1, wlp + WOFF_PW1,
                                                      polb1, nullptr, nullptr, z1ph, z1pl, HH, 1);
    tgemm<<<dim3(HH / 128, NR / 128), 256, tg_smem>>>(yvh, yvl, wh + WOFF_VW1, wlp + WOFF_VW1,
                                                      valb1, nullptr, nullptr, z1vh, z1vl, HH, 1);

    // MLP layer 2 (fp32 out)
    tgemm<<<dim3(HH / 128, NR / 128), 256, tg_smem>>>(z1ph, z1pl, wh + WOFF_PW2, wlp + WOFF_PW2,
                                                      polb2, nullptr, Z2pi, nullptr, nullptr, HH, 0);
    tgemm<<<dim3(HH / 128, NR / 128), 256, tg_smem>>>(z1vh, z1vl, wh + WOFF_VW2, wlp + WOFF_VW2,
                                                      valb2, nullptr, Z2vf, nullptr, nullptr, HH, 0);

    // heads
    head_kernel<<<NR, 128>>>(Z2pi, Z2vf, aw, ab, cw, cb, out);
}